// round 1
// baseline (speedup 1.0000x reference)
#include <cuda_runtime.h>
#include <math.h>

// Problem constants (fixed by setup_inputs)
#define NB   16
#define CIN  256
#define HS   64          // low-res H=W
#define HF   512         // full-res
#define FD   8

// Scratch buffers (no allocation allowed -> __device__ globals)
__device__ float g_h   [(size_t)NB * CIN * HS * HS];          // 64 MB
__device__ float g_hm  [(size_t)NB * CIN * HS * HS];          // 64 MB
__device__ float g_flow[(size_t)NB * 2 * HS * HS];            // 0.5 MB
__device__ float g_mask[(size_t)NB * HS * HS * 576];          // 151 MB, channel-last (N,H,W,576)

// ---------------------------------------------------------------------------
// conv_big: 3x3 conv, Ci=256, pad=1, EqualConv scale 1/48, optional relu.
// Block: 64 output channels x 16x16 pixels. 256 threads, each 16co x 4px.
// chanLast=1 writes (N,H,W,Co) (used for the mask so fuse_k reads coalesced).
// ---------------------------------------------------------------------------
__global__ __launch_bounds__(256, 2) void conv_big(
    const float* __restrict__ in, const float* __restrict__ wgt,
    const float* __restrict__ bias, float* __restrict__ out,
    int Co, int doRelu, int chanLast)
{
    __shared__ float s_in[8][18][19];
    __shared__ float s_w[8][64][9];

    const int tid = threadIdx.x;
    const int n = blockIdx.z;
    const int coBase = blockIdx.y * 64;
    const int sbx = blockIdx.x & 3, sby = blockIdx.x >> 2;
    const int pg = tid & 63, cg = tid >> 6;      // cg uniform per warp
    const int row = pg >> 2, xq = (pg & 3) * 4;

    float acc[16][4];
#pragma unroll
    for (int a = 0; a < 16; a++)
#pragma unroll
        for (int b = 0; b < 4; b++) acc[a][b] = 0.f;

    const float* inN = in + (size_t)n * CIN * HS * HS;

    for (int c0 = 0; c0 < CIN; c0 += 8) {
        // input halo tile 8 x 18 x 18 (zero-padded)
        for (int i = tid; i < 8 * 18 * 18; i += 256) {
            int ci = i / 324, rem = i % 324, r = rem / 18, c = rem % 18;
            int gy = sby * 16 - 1 + r, gx = sbx * 16 - 1 + c;
            float v = 0.f;
            if ((unsigned)gy < 64u && (unsigned)gx < 64u)
                v = inN[(size_t)(c0 + ci) * 4096 + gy * 64 + gx];
            s_in[ci][r][c] = v;
        }
        // weights 8ci x 64co x 9
        for (int i = tid; i < 8 * 64 * 9; i += 256) {
            int co = i / 72, rem = i % 72, ci = rem / 9, k = rem % 9;
            s_w[ci][co][k] = wgt[((size_t)(coBase + co) * CIN + c0 + ci) * 9 + k];
        }
        __syncthreads();

        for (int ci = 0; ci < 8; ci++) {
            float iv[3][6];
#pragma unroll
            for (int r2 = 0; r2 < 3; r2++)
#pragma unroll
                for (int c2 = 0; c2 < 6; c2++)
                    iv[r2][c2] = s_in[ci][row + r2][xq + c2];
#pragma unroll
            for (int cc = 0; cc < 16; cc++) {
                const int col = cg * 16 + cc;      // warp-uniform -> broadcast
                float w0 = s_w[ci][col][0], w1 = s_w[ci][col][1], w2 = s_w[ci][col][2];
                float w3 = s_w[ci][col][3], w4 = s_w[ci][col][4], w5 = s_w[ci][col][5];
                float w6 = s_w[ci][col][6], w7 = s_w[ci][col][7], w8 = s_w[ci][col][8];
#pragma unroll
                for (int p = 0; p < 4; p++) {
                    float s = acc[cc][p];
                    s = fmaf(iv[0][p    ], w0, s);
                    s = fmaf(iv[0][p + 1], w1, s);
                    s = fmaf(iv[0][p + 2], w2, s);
                    s = fmaf(iv[1][p    ], w3, s);
                    s = fmaf(iv[1][p + 1], w4, s);
                    s = fmaf(iv[1][p + 2], w5, s);
                    s = fmaf(iv[2][p    ], w6, s);
                    s = fmaf(iv[2][p + 1], w7, s);
                    s = fmaf(iv[2][p + 2], w8, s);
                    acc[cc][p] = s;
                }
            }
        }
        __syncthreads();
    }

    const float scale = 1.0f / 48.0f;              // 1/sqrt(256*9)
    const int py = sby * 16 + row, px0 = sbx * 16 + xq;
#pragma unroll
    for (int cc = 0; cc < 16; cc++) {
        const int co = coBase + cg * 16 + cc;
        const float b = bias[co];
#pragma unroll
        for (int p = 0; p < 4; p++) {
            float v = acc[cc][p] * scale + b;
            if (doRelu) v = fmaxf(v, 0.f);
            size_t pix = (size_t)py * 64 + px0 + p;
            if (chanLast)
                out[((size_t)n * 4096 + pix) * Co + co] = v;
            else
                out[((size_t)n * Co + co) * 4096 + pix] = v;
        }
    }
}

// ---------------------------------------------------------------------------
// conv_small: 3x3 conv 256 -> 2 (flow head). One pixel per thread.
// ---------------------------------------------------------------------------
__global__ __launch_bounds__(256) void conv_small(
    const float* __restrict__ in, const float* __restrict__ wgt,
    const float* __restrict__ bias, float* __restrict__ out)
{
    __shared__ float s_in[8][18][19];
    __shared__ float s_w[8][2][9];

    const int tid = threadIdx.x;
    const int n = blockIdx.z;
    const int sbx = blockIdx.x & 3, sby = blockIdx.x >> 2;
    const int row = tid >> 4, cx = tid & 15;

    float acc0 = 0.f, acc1 = 0.f;
    const float* inN = in + (size_t)n * CIN * HS * HS;

    for (int c0 = 0; c0 < CIN; c0 += 8) {
        for (int i = tid; i < 8 * 18 * 18; i += 256) {
            int ci = i / 324, rem = i % 324, r = rem / 18, c = rem % 18;
            int gy = sby * 16 - 1 + r, gx = sbx * 16 - 1 + c;
            float v = 0.f;
            if ((unsigned)gy < 64u && (unsigned)gx < 64u)
                v = inN[(size_t)(c0 + ci) * 4096 + gy * 64 + gx];
            s_in[ci][r][c] = v;
        }
        for (int i = tid; i < 8 * 2 * 9; i += 256) {
            int co = i / 72, rem = i % 72, ci = rem / 9, k = rem % 9;
            s_w[ci][co][k] = wgt[((size_t)co * CIN + c0 + ci) * 9 + k];
        }
        __syncthreads();

        for (int ci = 0; ci < 8; ci++) {
            float iv[3][3];
#pragma unroll
            for (int r2 = 0; r2 < 3; r2++)
#pragma unroll
                for (int c2 = 0; c2 < 3; c2++)
                    iv[r2][c2] = s_in[ci][row + r2][cx + c2];
#pragma unroll
            for (int k = 0; k < 9; k++) {
                acc0 = fmaf(iv[k / 3][k % 3], s_w[ci][0][k], acc0);
                acc1 = fmaf(iv[k / 3][k % 3], s_w[ci][1][k], acc1);
            }
        }
        __syncthreads();
    }

    const float scale = 1.0f / 48.0f;
    const int py = sby * 16 + row, px = sbx * 16 + cx;
    const size_t pix = (size_t)py * 64 + px;
    out[((size_t)n * 2 + 0) * 4096 + pix] = acc0 * scale + bias[0];
    out[((size_t)n * 2 + 1) * 4096 + pix] = acc1 * scale + bias[1];
}

// ---------------------------------------------------------------------------
// fuse_k: softmax convex upsample + identity grid + affine + border bilinear
// grid_sample + write all four outputs. Block = (y, u, n), 512 threads = row.
// ---------------------------------------------------------------------------
__global__ __launch_bounds__(512) void fuse_k(
    const float* __restrict__ img, const float* __restrict__ warp,
    float* __restrict__ outBuf)
{
    __shared__ float s_flow[2][3][66];   // 8*flow_lr rows y-1..y+1, zero-padded
    __shared__ float s_A[6];

    const int y = blockIdx.x, u = blockIdx.y, n = blockIdx.z;
    const int tid = threadIdx.x;

    if (tid < 6) s_A[tid] = warp[n * 6 + tid];
    for (int i = tid; i < 2 * 3 * 66; i += 512) {
        int c = i / 198, rem = i % 198, r = rem / 66, xx = rem % 66 - 1;
        int yy = y - 1 + r;
        float v = 0.f;
        if ((unsigned)yy < 64u && (unsigned)xx < 64u)
            v = 8.0f * g_flow[(((size_t)n * 2 + c) * 64 + yy) * 64 + xx];
        s_flow[c][r][xx + 1] = v;
    }
    __syncthreads();

    const int x = tid >> 3, v = tid & 7;

    // softmax over 9 kernel taps (channel-last mask -> coalesced)
    const float* m = &g_mask[((size_t)n * 4096 + (size_t)y * 64 + x) * 576 + u * 8 + v];
    float mk[9];
#pragma unroll
    for (int k = 0; k < 9; k++) mk[k] = m[k * 64];
    float mx = mk[0];
#pragma unroll
    for (int k = 1; k < 9; k++) mx = fmaxf(mx, mk[k]);
    float ssum = 0.f;
#pragma unroll
    for (int k = 0; k < 9; k++) { mk[k] = __expf(mk[k] - mx); ssum += mk[k]; }
    const float inv = 1.0f / ssum;

    float dx = 0.f, dy = 0.f;
#pragma unroll
    for (int k = 0; k < 9; k++) {
        const int ki = k / 3, kj = k % 3;
        const float w = mk[k] * inv;
        dx = fmaf(w, s_flow[0][ki][x + kj], dx);
        dy = fmaf(w, s_flow[1][ki][x + kj], dy);
    }

    const int xf = x * 8 + v, yf = y * 8 + u;
    const float gx = (xf + 0.5f) * (2.0f / 512.0f) - 1.0f + dx;
    const float gy = (yf + 0.5f) * (2.0f / 512.0f) - 1.0f + dy;
    const float fx = s_A[0] * gx + s_A[1] * gy + s_A[2];
    const float fy = s_A[3] * gx + s_A[4] * gy + s_A[5];

    // border bilinear sample from img (align_corners=False)
    float px = fminf(fmaxf((fx + 1.0f) * 256.0f - 0.5f, 0.f), 511.f);
    float py = fminf(fmaxf((fy + 1.0f) * 256.0f - 0.5f, 0.f), 511.f);
    float x0f = floorf(px), y0f = floorf(py);
    float wx = px - x0f, wy = py - y0f;
    int x0 = (int)x0f, y0 = (int)y0f;
    int x1 = min(x0 + 1, 511), y1 = min(y0 + 1, 511);

    const float* imN = img + (size_t)n * 3 * HF * HF;
#pragma unroll
    for (int c = 0; c < 3; c++) {
        const float* p = imN + (size_t)c * HF * HF;
        float g00 = p[(size_t)y0 * HF + x0], g01 = p[(size_t)y0 * HF + x1];
        float g10 = p[(size_t)y1 * HF + x0], g11 = p[(size_t)y1 * HF + x1];
        float top = g00 + wx * (g01 - g00);
        float bot = g10 + wx * (g11 - g10);
        float val = top + wy * (bot - top);
        outBuf[(((size_t)n * 3 + c) * HF + yf) * HF + xf] = val;
    }

    // tuple layout: out | flow | delta_flow | flow
    const size_t OFS_FLOW  = (size_t)NB * 3 * HF * HF;                 // 12582912
    const size_t OFS_DELTA = OFS_FLOW + (size_t)NB * HF * HF * 2;      // 20971520
    const size_t OFS_FLOW2 = OFS_DELTA + (size_t)NB * HF * HF * 2;     // 29360128
    const size_t fidx = ((size_t)n * HF * HF + (size_t)yf * HF + xf) * 2;
    outBuf[OFS_FLOW  + fidx] = fx;  outBuf[OFS_FLOW  + fidx + 1] = fy;
    outBuf[OFS_DELTA + fidx] = dx;  outBuf[OFS_DELTA + fidx + 1] = dy;
    outBuf[OFS_FLOW2 + fidx] = fx;  outBuf[OFS_FLOW2 + fidx + 1] = fy;
}

// ---------------------------------------------------------------------------
extern "C" void kernel_launch(void* const* d_in, const int* in_sizes, int n_in,
                              void* d_out, int out_size)
{
    const float* img       = (const float*)d_in[0];
    const float* features  = (const float*)d_in[1];
    const float* base_warp = (const float*)d_in[2];
    const float* w_f1 = (const float*)d_in[3];
    const float* b_f1 = (const float*)d_in[4];
    const float* w_f2 = (const float*)d_in[5];
    const float* b_f2 = (const float*)d_in[6];
    const float* w_m1 = (const float*)d_in[7];
    const float* b_m1 = (const float*)d_in[8];
    const float* w_m2 = (const float*)d_in[9];
    const float* b_m2 = (const float*)d_in[10];
    float* out = (float*)d_out;

    float *ph, *phm, *pflow, *pmask;
    cudaGetSymbolAddress((void**)&ph, g_h);
    cudaGetSymbolAddress((void**)&phm, g_hm);
    cudaGetSymbolAddress((void**)&pflow, g_flow);
    cudaGetSymbolAddress((void**)&pmask, g_mask);

    conv_big<<<dim3(16, 4, NB), 256>>>(features, w_f1, b_f1, ph, 256, 1, 0);
    conv_big<<<dim3(16, 4, NB), 256>>>(features, w_m1, b_m1, phm, 256, 1, 0);
    conv_small<<<dim3(16, 1, NB), 256>>>(ph, w_f2, b_f2, pflow);
    conv_big<<<dim3(16, 9, NB), 256>>>(phm, w_m2, b_m2, pmask, 576, 0, 1);
    fuse_k<<<dim3(64, 8, NB), 512>>>(img, base_warp, out);
}

// round 5
// speedup vs baseline: 4.1085x; 4.1085x over previous
#include <cuda_runtime.h>
#include <cuda_fp16.h>
#include <cstdint>
#include <math.h>

#define NB   16
#define CIN  256
#define HS   64
#define HF   512
#define KEXT 6912            // 9 taps * 256 ci * 3 split slots
#define CHEXT 768            // 256 ci * 3 per tap
#define NCH  108             // KEXT / 64

// ---------------- scratch (__device__ globals; no allocation allowed) ------
__device__ __align__(16) __half g_featx[(size_t)NB * 66 * 66 * CHEXT]; // padded ext features
__device__ __align__(16) __half g_hmx  [(size_t)NB * 66 * 66 * CHEXT]; // padded ext hm
__device__ float g_h   [(size_t)NB * CIN * HS * HS];                   // f1 out fp32 NCHW
__device__ float g_flow[(size_t)NB * 2 * HS * HS];
__device__ float g_mask[(size_t)NB * HS * HS * 576];                   // channel-last
__device__ __align__(16) __half g_wf1x[256 * KEXT];
__device__ __align__(16) __half g_wm1x[256 * KEXT];
__device__ __align__(16) __half g_wm2x[576 * KEXT];

// ---------------- helpers ----------------
__device__ __forceinline__ uint32_t smem_u32(const void* p) {
    uint32_t a;
    asm("{ .reg .u64 t; cvta.to.shared.u64 t, %1; cvt.u32.u64 %0, t; }" : "=r"(a) : "l"(p));
    return a;
}
__device__ __forceinline__ void cpasync16(uint32_t dst, const void* src) {
    asm volatile("cp.async.cg.shared.global [%0], [%1], 16;" :: "r"(dst), "l"(src) : "memory");
}
#define CP_COMMIT() asm volatile("cp.async.commit_group;" ::: "memory")
#define CP_WAIT1()  asm volatile("cp.async.wait_group 1;" ::: "memory")
#define SWZ(o) ((o) ^ (((o) >> 3) & 0x70))

#define LDMX4(r0, r1, r2, r3, addr) \
    asm volatile("ldmatrix.sync.aligned.m8n8.x4.shared.b16 {%0,%1,%2,%3}, [%4];" \
        : "=r"(r0), "=r"(r1), "=r"(r2), "=r"(r3) : "r"(addr))

#define MMA16816(c, a, b) \
    asm volatile("mma.sync.aligned.m16n8k16.row.col.f32.f16.f16.f32 " \
        "{%0,%1,%2,%3},{%4,%5,%6,%7},{%8,%9},{%0,%1,%2,%3};" \
        : "+f"((c)[0]), "+f"((c)[1]), "+f"((c)[2]), "+f"((c)[3]) \
        : "r"((a)[0]), "r"((a)[1]), "r"((a)[2]), "r"((a)[3]), "r"((b)[0]), "r"((b)[1]))

__device__ __forceinline__ void split_h(float v, unsigned short& h, unsigned short& l) {
    __half hh = __float2half_rn(v);
    __half ll = __float2half_rn(v - __half2float(hh));
    h = __half_as_ushort(hh);
    l = __half_as_ushort(ll);
}

// ---------------- prep kernels ----------------
__global__ void k_border() {   // zero 1-px border of both ext buffers
    int p = blockIdx.x, n = blockIdx.y;
    int y, x;
    if (p < 66)       { y = 0;  x = p; }
    else if (p < 132) { y = 65; x = p - 66; }
    else if (p < 196) { y = p - 132 + 1; x = 0; }
    else              { y = p - 196 + 1; x = 65; }
    __half* buf = blockIdx.z ? g_hmx : g_featx;
    uint2* dst = (uint2*)(buf + (((size_t)n * 66 + y) * 66 + x) * CHEXT);
    if (threadIdx.x < 192) dst[threadIdx.x] = make_uint2(0u, 0u);
}

__global__ void k_featx(const float* __restrict__ feat) {
    __shared__ float s[32][33];
    const int n = blockIdx.z, pb = blockIdx.x * 32, cb = blockIdx.y * 32;
    const int tx = threadIdx.x & 31, ty = threadIdx.x >> 5;
#pragma unroll
    for (int i = 0; i < 4; i++)
        s[ty + i * 8][tx] = feat[((size_t)n * 256 + cb + ty + i * 8) * 4096 + pb + tx];
    __syncthreads();
    const int pl = threadIdx.x >> 3, c4 = (threadIdx.x & 7) * 4;
    const int pix = pb + pl, y = pix >> 6, x = pix & 63;
    char* dst = (char*)(g_featx + (((size_t)n * 66 + y + 1) * 66 + (x + 1)) * CHEXT)
                + (size_t)(cb + c4) * 6;
    unsigned short h[4], l[4];
#pragma unroll
    for (int k = 0; k < 4; k++) split_h(s[c4 + k][pl], h[k], l[k]);
    uint2 w0, w1;  // 12 halves: h0 l0 h0 | h1 l1 h1 | h2 l2 h2 | h3 l3 h3
    w0.x = (uint32_t)h[0] | ((uint32_t)l[0] << 16);
    w0.y = (uint32_t)h[0] | ((uint32_t)h[1] << 16);
    uint32_t w2 = (uint32_t)l[1] | ((uint32_t)h[1] << 16);
    w1.x = (uint32_t)h[2] | ((uint32_t)l[2] << 16);
    w1.y = (uint32_t)h[2] | ((uint32_t)h[3] << 16);
    uint32_t w5 = (uint32_t)l[3] | ((uint32_t)h[3] << 16);
    ((uint2*)dst)[0] = w0;
    ((uint32_t*)dst)[2] = w2;
    ((uint2*)(dst + 12))[0] = w1;
    ((uint32_t*)dst)[5] = w5;
}

__global__ void k_wext(const float* __restrict__ w, __half* __restrict__ wx) {
    const int co = blockIdx.x, tap = blockIdx.y, ci = threadIdx.x;
    float v = w[((size_t)co * 256 + ci) * 9 + tap];
    unsigned short h, l;
    split_h(v, h, l);
    unsigned short* p = (unsigned short*)(wx + (size_t)co * KEXT + tap * CHEXT + ci * 3);
    p[0] = h; p[1] = h; p[2] = l;      // slots: (xh*wh) (xl*wh) (xh*wl)
}

// ---------------- HMMA implicit-GEMM conv ----------------
// MODE 0: fp32 NCHW + relu. MODE 1: split-fp16 ext + relu. MODE 2: chan-last fp32.
template<int N_CTA, int MODE>
__global__ __launch_bounds__(256, 1) void gemm_conv(
    const __half* __restrict__ Aext, const __half* __restrict__ Bw,
    const float* __restrict__ bias, void* __restrict__ outp)
{
    constexpr int NW = N_CTA / 16;            // n8 frags per warp
    constexpr int STAGE_A = 128 * 128;        // bytes
    constexpr int STAGE_B = N_CTA * 128;
    constexpr int STAGE = STAGE_A + STAGE_B;

    extern __shared__ __align__(16) char smraw[];
    uint32_t sb0 = (smem_u32(smraw) + 1023) & ~1023u;

    const int tid = threadIdx.x;
    const int n    = blockIdx.y >> 5;
    const int yblk = blockIdx.y & 31;
    const int pix0 = yblk * 128;
    const int co_base = blockIdx.x * N_CTA;

    auto load_chunk = [&](int kk, int st) {
        const int tap = kk / 12, cg = kk % 12;
        const int dy = tap / 3, dx = tap % 3;
        {   // A: 128 pixel rows x 128B
            const int r = tid >> 1, g0 = (tid & 1) * 4;
            const int p = pix0 + r, y = p >> 6, x = p & 63;
            const char* src = (const char*)Aext
                + (((size_t)n * 66 + y + dy) * 66 + (x + dx)) * (CHEXT * 2)
                + (size_t)cg * 128 + g0 * 16;
            const uint32_t base = sb0 + st * STAGE;
#pragma unroll
            for (int i = 0; i < 4; i++)
                cpasync16(base + SWZ((uint32_t)(r * 128 + (g0 + i) * 16)), src + i * 16);
        }
        {   // B: N_CTA co rows x 128B
            const uint32_t base = sb0 + st * STAGE + STAGE_A;
            for (int idx = tid; idx < N_CTA * 8; idx += 256) {
                const int r = idx >> 3, g = idx & 7;
                const char* src = (const char*)Bw
                    + ((size_t)(co_base + r) * KEXT + (size_t)tap * CHEXT + cg * 64) * 2
                    + g * 16;
                cpasync16(base + SWZ((uint32_t)(r * 128 + g * 16)), src + g * 0 /*keep*/);
                // note: offset already in src
            }
        }
    };

    const int l = tid & 31, wid = tid >> 5;
    const int wm = wid >> 1, wn = wid & 1;

    float acc[2][NW][4];
#pragma unroll
    for (int mi = 0; mi < 2; mi++)
#pragma unroll
        for (int j = 0; j < NW; j++)
#pragma unroll
            for (int q = 0; q < 4; q++) acc[mi][j][q] = 0.f;

    load_chunk(0, 0); CP_COMMIT();
    load_chunk(1, 1); CP_COMMIT();

    const int arow  = wm * 32 + (l & 7) + ((l >> 3) & 1) * 8;  // + mi*16
    const int aklan = ((l >> 4) & 1) * 16;                     // bytes
    const int brow0 = wn * (NW * 8) + (l & 7) + ((l >> 4) & 1) * 8; // + j2*16
    const int bklan = ((l >> 3) & 1) * 16;

    for (int kk = 0; kk < NCH; kk++) {
        const int st = kk % 3;
        CP_WAIT1();
        __syncthreads();
        const uint32_t a_tile = sb0 + st * STAGE;
        const uint32_t b_tile = a_tile + STAGE_A;
#pragma unroll
        for (int ks = 0; ks < 4; ks++) {
            uint32_t a[2][4];
#pragma unroll
            for (int mi = 0; mi < 2; mi++)
                LDMX4(a[mi][0], a[mi][1], a[mi][2], a[mi][3],
                      a_tile + SWZ((uint32_t)((arow + mi * 16) * 128 + ks * 32 + aklan)));
            uint32_t b[NW][2];
#pragma unroll
            for (int j2 = 0; j2 < NW / 2; j2++) {
                uint32_t r0, r1, r2, r3;
                LDMX4(r0, r1, r2, r3,
                      b_tile + SWZ((uint32_t)((brow0 + j2 * 16) * 128 + ks * 32 + bklan)));
                b[j2 * 2][0] = r0; b[j2 * 2][1] = r1;
                b[j2 * 2 + 1][0] = r2; b[j2 * 2 + 1][1] = r3;
            }
#pragma unroll
            for (int mi = 0; mi < 2; mi++)
#pragma unroll
                for (int j = 0; j < NW; j++)
                    MMA16816(acc[mi][j], a[mi], b[j]);
        }
        const int kn = kk + 2;
        if (kn < NCH) load_chunk(kn, kn % 3);
        CP_COMMIT();
    }

    // ---------------- epilogue ----------------
    const float scale = 1.0f / 48.0f;
    const int r0 = l >> 2, c0 = (l & 3) * 2;
    float2 bs[NW];
#pragma unroll
    for (int j = 0; j < NW; j++) {
        const int co = co_base + wn * NW * 8 + j * 8 + c0;
        bs[j].x = __ldg(&bias[co]); bs[j].y = __ldg(&bias[co + 1]);
    }
#pragma unroll
    for (int mi = 0; mi < 2; mi++) {
#pragma unroll
        for (int h = 0; h < 2; h++) {
            const int p = pix0 + wm * 32 + mi * 16 + r0 + 8 * h;
            const int y = p >> 6, x = p & 63;
#pragma unroll
            for (int j = 0; j < NW; j++) {
                const int co = co_base + wn * NW * 8 + j * 8 + c0;
                float v0 = acc[mi][j][2 * h]     * scale + bs[j].x;
                float v1 = acc[mi][j][2 * h + 1] * scale + bs[j].y;
                if (MODE != 2) { v0 = fmaxf(v0, 0.f); v1 = fmaxf(v1, 0.f); }
                if (MODE == 0) {
                    ((float*)outp)[((size_t)n * 256 + co) * 4096 + p] = v0;
                    ((float*)outp)[((size_t)n * 256 + co + 1) * 4096 + p] = v1;
                } else if (MODE == 1) {
                    unsigned short h0, l0, h1, l1;
                    split_h(v0, h0, l0); split_h(v1, h1, l1);
                    uint32_t* dst = (uint32_t*)((char*)outp
                        + (((size_t)n * 66 + y + 1) * 66 + (x + 1)) * (CHEXT * 2)
                        + (size_t)co * 6);
                    dst[0] = (uint32_t)h0 | ((uint32_t)l0 << 16);
                    dst[1] = (uint32_t)h0 | ((uint32_t)h1 << 16);
                    dst[2] = (uint32_t)l1 | ((uint32_t)h1 << 16);
                } else {
                    ((float2*)((float*)outp + ((size_t)n * 4096 + p) * 576 + co))[0]
                        = make_float2(v0, v1);
                }
            }
        }
    }
}

// ---------------- f2: 3x3 conv 256 -> 2 (fp32 FFMA) ----------------
__global__ __launch_bounds__(256) void conv_small(
    const float* __restrict__ in, const float* __restrict__ wgt,
    const float* __restrict__ bias, float* __restrict__ out)
{
    __shared__ float s_in[8][18][19];
    __shared__ float s_w[8][2][9];
    const int tid = threadIdx.x, n = blockIdx.z;
    const int sbx = blockIdx.x & 3, sby = blockIdx.x >> 2;
    const int row = tid >> 4, cx = tid & 15;
    float acc0 = 0.f, acc1 = 0.f;
    const float* inN = in + (size_t)n * CIN * HS * HS;

    for (int c0 = 0; c0 < CIN; c0 += 8) {
        for (int i = tid; i < 8 * 18 * 18; i += 256) {
            int ci = i / 324, rem = i % 324, r = rem / 18, c = rem % 18;
            int gy = sby * 16 - 1 + r, gx = sbx * 16 - 1 + c;
            float v = 0.f;
            if ((unsigned)gy < 64u && (unsigned)gx < 64u)
                v = inN[(size_t)(c0 + ci) * 4096 + gy * 64 + gx];
            s_in[ci][r][c] = v;
        }
        for (int i = tid; i < 8 * 2 * 9; i += 256) {
            int co = i / 72, rem = i % 72, ci = rem / 9, k = rem % 9;
            s_w[ci][co][k] = wgt[((size_t)co * CIN + c0 + ci) * 9 + k];
        }
        __syncthreads();
        for (int ci = 0; ci < 8; ci++) {
            float iv[3][3];
#pragma unroll
            for (int r2 = 0; r2 < 3; r2++)
#pragma unroll
                for (int c2 = 0; c2 < 3; c2++)
                    iv[r2][c2] = s_in[ci][row + r2][cx + c2];
#pragma unroll
            for (int k = 0; k < 9; k++) {
                acc0 = fmaf(iv[k / 3][k % 3], s_w[ci][0][k], acc0);
                acc1 = fmaf(iv[k / 3][k % 3], s_w[ci][1][k], acc1);
            }
        }
        __syncthreads();
    }
    const float scale = 1.0f / 48.0f;
    const int py = sby * 16 + row, px = sbx * 16 + cx;
    const size_t pix = (size_t)py * 64 + px;
    out[((size_t)n * 2 + 0) * 4096 + pix] = acc0 * scale + bias[0];
    out[((size_t)n * 2 + 1) * 4096 + pix] = acc1 * scale + bias[1];
}

// ---------------- fused upsample + affine + grid_sample ----------------
__global__ __launch_bounds__(512) void fuse_k(
    const float* __restrict__ img, const float* __restrict__ warp,
    float* __restrict__ outBuf)
{
    __shared__ float s_flow[2][3][66];
    __shared__ float s_A[6];
    const int y = blockIdx.x, u = blockIdx.y, n = blockIdx.z;
    const int tid = threadIdx.x;

    if (tid < 6) s_A[tid] = warp[n * 6 + tid];
    for (int i = tid; i < 2 * 3 * 66; i += 512) {
        int c = i / 198, rem = i % 198, r = rem / 66, xx = rem % 66 - 1;
        int yy = y - 1 + r;
        float v = 0.f;
        if ((unsigned)yy < 64u && (unsigned)xx < 64u)
            v = 8.0f * g_flow[(((size_t)n * 2 + c) * 64 + yy) * 64 + xx];
        s_flow[c][r][xx + 1] = v;
    }
    __syncthreads();

    const int x = tid >> 3, v = tid & 7;
    const float* m = &g_mask[((size_t)n * 4096 + (size_t)y * 64 + x) * 576 + u * 8 + v];
    float mk[9];
#pragma unroll
    for (int k = 0; k < 9; k++) mk[k] = m[k * 64];
    float mx = mk[0];
#pragma unroll
    for (int k = 1; k < 9; k++) mx = fmaxf(mx, mk[k]);
    float ssum = 0.f;
#pragma unroll
    for (int k = 0; k < 9; k++) { mk[k] = __expf(mk[k] - mx); ssum += mk[k]; }
    const float inv = 1.0f / ssum;

    float dx = 0.f, dy = 0.f;
#pragma unroll
    for (int k = 0; k < 9; k++) {
        const int ki = k / 3, kj = k % 3;
        const float w = mk[k] * inv;
        dx = fmaf(w, s_flow[0][ki][x + kj], dx);
        dy = fmaf(w, s_flow[1][ki][x + kj], dy);
    }

    const int xf = x * 8 + v, yf = y * 8 + u;
    const float gx = (xf + 0.5f) * (2.0f / 512.0f) - 1.0f + dx;
    const float gy = (yf + 0.5f) * (2.0f / 512.0f) - 1.0f + dy;
    const float fx = s_A[0] * gx + s_A[1] * gy + s_A[2];
    const float fy = s_A[3] * gx + s_A[4] * gy + s_A[5];

    float px = fminf(fmaxf((fx + 1.0f) * 256.0f - 0.5f, 0.f), 511.f);
    float py = fminf(fmaxf((fy + 1.0f) * 256.0f - 0.5f, 0.f), 511.f);
    float x0f = floorf(px), y0f = floorf(py);
    float wx = px - x0f, wy = py - y0f;
    int x0 = (int)x0f, y0 = (int)y0f;
    int x1 = min(x0 + 1, 511), y1 = min(y0 + 1, 511);

    const float* imN = img + (size_t)n * 3 * HF * HF;
#pragma unroll
    for (int c = 0; c < 3; c++) {
        const float* p = imN + (size_t)c * HF * HF;
        float g00 = p[(size_t)y0 * HF + x0], g01 = p[(size_t)y0 * HF + x1];
        float g10 = p[(size_t)y1 * HF + x0], g11 = p[(size_t)y1 * HF + x1];
        float top = g00 + wx * (g01 - g00);
        float bot = g10 + wx * (g11 - g10);
        outBuf[(((size_t)n * 3 + c) * HF + yf) * HF + xf] = top + wy * (bot - top);
    }

    const size_t OFS_FLOW  = (size_t)NB * 3 * HF * HF;
    const size_t OFS_DELTA = OFS_FLOW + (size_t)NB * HF * HF * 2;
    const size_t OFS_FLOW2 = OFS_DELTA + (size_t)NB * HF * HF * 2;
    const size_t fidx = ((size_t)n * HF * HF + (size_t)yf * HF + xf) * 2;
    outBuf[OFS_FLOW  + fidx] = fx;  outBuf[OFS_FLOW  + fidx + 1] = fy;
    outBuf[OFS_DELTA + fidx] = dx;  outBuf[OFS_DELTA + fidx + 1] = dy;
    outBuf[OFS_FLOW2 + fidx] = fx;  outBuf[OFS_FLOW2 + fidx + 1] = fy;
}

// ---------------------------------------------------------------------------
extern "C" void kernel_launch(void* const* d_in, const int* in_sizes, int n_in,
                              void* d_out, int out_size)
{
    const float* img       = (const float*)d_in[0];
    const float* features  = (const float*)d_in[1];
    const float* base_warp = (const float*)d_in[2];
    const float* w_f1 = (const float*)d_in[3];
    const float* b_f1 = (const float*)d_in[4];
    const float* w_f2 = (const float*)d_in[5];
    const float* b_f2 = (const float*)d_in[6];
    const float* w_m1 = (const float*)d_in[7];
    const float* b_m1 = (const float*)d_in[8];
    const float* w_m2 = (const float*)d_in[9];
    const float* b_m2 = (const float*)d_in[10];
    float* out = (float*)d_out;

    void *p_featx, *p_hmx, *p_h, *p_flow, *p_mask, *p_wf1x, *p_wm1x, *p_wm2x;
    cudaGetSymbolAddress(&p_featx, g_featx);
    cudaGetSymbolAddress(&p_hmx,   g_hmx);
    cudaGetSymbolAddress(&p_h,     g_h);
    cudaGetSymbolAddress(&p_flow,  g_flow);
    cudaGetSymbolAddress(&p_mask,  g_mask);
    cudaGetSymbolAddress(&p_wf1x,  g_wf1x);
    cudaGetSymbolAddress(&p_wm1x,  g_wm1x);
    cudaGetSymbolAddress(&p_wm2x,  g_wm2x);

    const int SM128 = 1024 + 3 * (16384 + 128 * 128);   // 99328
    const int SM192 = 1024 + 3 * (16384 + 192 * 128);   // 123904
    cudaFuncSetAttribute(gemm_conv<128, 0>, cudaFuncAttributeMaxDynamicSharedMemorySize, SM128);
    cudaFuncSetAttribute(gemm_conv<128, 1>, cudaFuncAttributeMaxDynamicSharedMemorySize, SM128);
    cudaFuncSetAttribute(gemm_conv<192, 2>, cudaFuncAttributeMaxDynamicSharedMemorySize, SM192);

    k_border<<<dim3(260, 16, 2), 256>>>();
    k_featx<<<dim3(128, 8, 16), 256>>>(features);
    k_wext<<<dim3(256, 9), 256>>>(w_f1, (__half*)p_wf1x);
    k_wext<<<dim3(256, 9), 256>>>(w_m1, (__half*)p_wm1x);
    k_wext<<<dim3(576, 9), 256>>>(w_m2, (__half*)p_wm2x);

    gemm_conv<128, 0><<<dim3(2, 512), 256, SM128>>>(
        (const __half*)p_featx, (const __half*)p_wf1x, b_f1, p_h);
    gemm_conv<128, 1><<<dim3(2, 512), 256, SM128>>>(
        (const __half*)p_featx, (const __half*)p_wm1x, b_m1, p_hmx);
    conv_small<<<dim3(16, 1, NB), 256>>>((const float*)p_h, w_f2, b_f2, (float*)p_flow);
    gemm_conv<192, 2><<<dim3(3, 512), 256, SM192>>>(
        (const __half*)p_hmx, (const __half*)p_wm2x, b_m2, p_mask);
    fuse_k<<<dim3(64, 8, NB), 512>>>(img, base_warp, out);
}

// round 6
// speedup vs baseline: 4.9101x; 1.1951x over previous
#include <cuda_runtime.h>
#include <cuda_fp16.h>
#include <cstdint>
#include <math.h>

#define NB   16
#define CIN  256
#define HS   64
#define HF   512
#define KEXT 6912            // 9 taps * 256 ci * 3 split slots
#define CHEXT 768            // 256 ci * 3 per tap
#define NCH  108             // KEXT / 64

// ---------------- scratch (__device__ globals; no allocation allowed) ------
__device__ __align__(16) __half g_featx[(size_t)NB * 66 * 66 * CHEXT]; // padded ext features
__device__ __align__(16) __half g_hmx  [(size_t)NB * 66 * 66 * CHEXT]; // padded ext hm
__device__ float g_h   [(size_t)NB * CIN * HS * HS];                   // f1 out fp32 NCHW
__device__ float g_flow[(size_t)NB * 2 * HS * HS];
__device__ float g_mask[(size_t)NB * HS * HS * 576];                   // channel-last
__device__ __align__(16) __half g_w1x [512 * KEXT];                    // rows 0-255 f1, 256-511 m1
__device__ __align__(16) __half g_wm2x[576 * KEXT];

// ---------------- helpers ----------------
__device__ __forceinline__ uint32_t smem_u32(const void* p) {
    uint32_t a;
    asm("{ .reg .u64 t; cvta.to.shared.u64 t, %1; cvt.u32.u64 %0, t; }" : "=r"(a) : "l"(p));
    return a;
}
__device__ __forceinline__ void cpasync16(uint32_t dst, const void* src) {
    asm volatile("cp.async.cg.shared.global [%0], [%1], 16;" :: "r"(dst), "l"(src) : "memory");
}
#define CP_COMMIT() asm volatile("cp.async.commit_group;" ::: "memory")
#define CP_WAIT1()  asm volatile("cp.async.wait_group 1;" ::: "memory")
#define SWZ(o) ((o) ^ (((o) >> 3) & 0x70))

#define LDMX4(r0, r1, r2, r3, addr) \
    asm volatile("ldmatrix.sync.aligned.m8n8.x4.shared.b16 {%0,%1,%2,%3}, [%4];" \
        : "=r"(r0), "=r"(r1), "=r"(r2), "=r"(r3) : "r"(addr))

#define MMA16816(c, a, b) \
    asm volatile("mma.sync.aligned.m16n8k16.row.col.f32.f16.f16.f32 " \
        "{%0,%1,%2,%3},{%4,%5,%6,%7},{%8,%9},{%0,%1,%2,%3};" \
        : "+f"((c)[0]), "+f"((c)[1]), "+f"((c)[2]), "+f"((c)[3]) \
        : "r"((a)[0]), "r"((a)[1]), "r"((a)[2]), "r"((a)[3]), "r"((b)[0]), "r"((b)[1]))

__device__ __forceinline__ void split_h(float v, unsigned short& h, unsigned short& l) {
    __half hh = __float2half_rn(v);
    __half ll = __float2half_rn(v - __half2float(hh));
    h = __half_as_ushort(hh);
    l = __half_as_ushort(ll);
}

// ---------------- prep kernels ----------------
__global__ void k_border() {   // zero 1-px border of both ext buffers
    int p = blockIdx.x, n = blockIdx.y;
    int y, x;
    if (p < 66)       { y = 0;  x = p; }
    else if (p < 132) { y = 65; x = p - 66; }
    else if (p < 196) { y = p - 132 + 1; x = 0; }
    else              { y = p - 196 + 1; x = 65; }
    __half* buf = blockIdx.z ? g_hmx : g_featx;
    uint2* dst = (uint2*)(buf + (((size_t)n * 66 + y) * 66 + x) * CHEXT);
    if (threadIdx.x < 192) dst[threadIdx.x] = make_uint2(0u, 0u);
}

__global__ void k_featx(const float* __restrict__ feat) {
    __shared__ float s[32][33];
    const int n = blockIdx.z, pb = blockIdx.x * 32, cb = blockIdx.y * 32;
    const int tx = threadIdx.x & 31, ty = threadIdx.x >> 5;
#pragma unroll
    for (int i = 0; i < 4; i++)
        s[ty + i * 8][tx] = feat[((size_t)n * 256 + cb + ty + i * 8) * 4096 + pb + tx];
    __syncthreads();
    const int pl = threadIdx.x >> 3, c4 = (threadIdx.x & 7) * 4;
    const int pix = pb + pl, y = pix >> 6, x = pix & 63;
    char* dst = (char*)(g_featx + (((size_t)n * 66 + y + 1) * 66 + (x + 1)) * CHEXT)
                + (size_t)(cb + c4) * 6;
    unsigned short h[4], l[4];
#pragma unroll
    for (int k = 0; k < 4; k++) split_h(s[c4 + k][pl], h[k], l[k]);
    uint2 w0, w1;  // 12 halves: h0 l0 h0 | h1 l1 h1 | h2 l2 h2 | h3 l3 h3
    w0.x = (uint32_t)h[0] | ((uint32_t)l[0] << 16);
    w0.y = (uint32_t)h[0] | ((uint32_t)h[1] << 16);
    uint32_t w2 = (uint32_t)l[1] | ((uint32_t)h[1] << 16);
    w1.x = (uint32_t)h[2] | ((uint32_t)l[2] << 16);
    w1.y = (uint32_t)h[2] | ((uint32_t)h[3] << 16);
    uint32_t w5 = (uint32_t)l[3] | ((uint32_t)h[3] << 16);
    ((uint2*)dst)[0] = w0;
    ((uint32_t*)dst)[2] = w2;
    ((uint2*)(dst + 12))[0] = w1;
    ((uint32_t*)dst)[5] = w5;
}

__global__ void k_wext(const float* __restrict__ w, __half* __restrict__ wx) {
    const int co = blockIdx.x, tap = blockIdx.y, ci = threadIdx.x;
    float v = w[((size_t)co * 256 + ci) * 9 + tap];
    unsigned short h, l;
    split_h(v, h, l);
    unsigned short* p = (unsigned short*)(wx + (size_t)co * KEXT + tap * CHEXT + ci * 3);
    p[0] = h; p[1] = h; p[2] = l;      // slots: (xh*wh) (xl*wh) (xh*wl)
}

// ---------------- HMMA implicit-GEMM conv ----------------
// CTA tile 128(M) x N_CTA, 8 warps as 2(wm) x 4(wn), warp tile m64 x n(N_CTA/4).
// MODE 0 (fused f1+m1): blockIdx.x==0 -> fp32 NCHW + relu (g_h);
//                       blockIdx.x==1 -> split-fp16 ext + relu (g_hmx).
// MODE 2: channel-last fp32, no relu (mask).
template<int N_CTA, int MODE>
__global__ __launch_bounds__(256, 1) void gemm_conv(
    const __half* __restrict__ Aext, const __half* __restrict__ Bw,
    const float* __restrict__ bias0, const float* __restrict__ bias1,
    void* __restrict__ out0, void* __restrict__ out1)
{
    constexpr int NW = N_CTA / 32;            // n8 frags per warp (8 or 6)
    constexpr int STAGE_A = 128 * 128;        // bytes
    constexpr int STAGE_B = N_CTA * 128;
    constexpr int STAGE = STAGE_A + STAGE_B;

    extern __shared__ __align__(16) char smraw[];
    uint32_t sb0 = (smem_u32(smraw) + 1023) & ~1023u;

    const int tid = threadIdx.x;
    const int n    = blockIdx.y >> 5;
    const int pix0 = (blockIdx.y & 31) * 128;
    const int co_base = blockIdx.x * N_CTA;

    auto load_chunk = [&](int kk, int st) {
        const int tap = kk / 12, cg = kk % 12;
        const int dy = tap / 3, dx = tap % 3;
        {   // A: 128 pixel rows x 128B
            const int r = tid >> 1, g0 = (tid & 1) * 4;
            const int p = pix0 + r, y = p >> 6, x = p & 63;
            const char* src = (const char*)Aext
                + (((size_t)n * 66 + y + dy) * 66 + (x + dx)) * (CHEXT * 2)
                + (size_t)cg * 128 + g0 * 16;
            const uint32_t base = sb0 + st * STAGE;
#pragma unroll
            for (int i = 0; i < 4; i++)
                cpasync16(base + SWZ((uint32_t)(r * 128 + (g0 + i) * 16)), src + i * 16);
        }
        {   // B: N_CTA co rows x 128B
            const uint32_t base = sb0 + st * STAGE + STAGE_A;
            const char* srcb = (const char*)Bw + ((size_t)tap * CHEXT + cg * 64) * 2;
#pragma unroll
            for (int idx = tid; idx < N_CTA * 8; idx += 256) {
                const int r = idx >> 3, g = idx & 7;
                const char* src = srcb + (size_t)(co_base + r) * (KEXT * 2) + g * 16;
                cpasync16(base + SWZ((uint32_t)(r * 128 + g * 16)), src);
            }
        }
    };

    const int l = tid & 31, wid = tid >> 5;
    const int wm = wid >> 2, wn = wid & 3;

    float acc[4][NW][4];
#pragma unroll
    for (int mi = 0; mi < 4; mi++)
#pragma unroll
        for (int j = 0; j < NW; j++)
#pragma unroll
            for (int q = 0; q < 4; q++) acc[mi][j][q] = 0.f;

    load_chunk(0, 0); CP_COMMIT();
    load_chunk(1, 1); CP_COMMIT();

    const int arow  = wm * 64 + (l & 7) + ((l >> 3) & 1) * 8;          // + mi*16
    const int aklan = ((l >> 4) & 1) * 16;                             // bytes
    const int brow0 = wn * (N_CTA / 4) + (l & 7) + ((l >> 4) & 1) * 8; // + j2*16
    const int bklan = ((l >> 3) & 1) * 16;

    for (int kk = 0; kk < NCH; kk++) {
        const int st = kk % 3;
        CP_WAIT1();
        __syncthreads();
        const uint32_t a_tile = sb0 + st * STAGE;
        const uint32_t b_tile = a_tile + STAGE_A;
#pragma unroll
        for (int ks = 0; ks < 4; ks++) {
            uint32_t a[4][4];
#pragma unroll
            for (int mi = 0; mi < 4; mi++)
                LDMX4(a[mi][0], a[mi][1], a[mi][2], a[mi][3],
                      a_tile + SWZ((uint32_t)((arow + mi * 16) * 128 + ks * 32 + aklan)));
            uint32_t b[NW][2];
#pragma unroll
            for (int j2 = 0; j2 < NW / 2; j2++) {
                uint32_t r0, r1, r2, r3;
                LDMX4(r0, r1, r2, r3,
                      b_tile + SWZ((uint32_t)((brow0 + j2 * 16) * 128 + ks * 32 + bklan)));
                b[j2 * 2][0] = r0; b[j2 * 2][1] = r1;
                b[j2 * 2 + 1][0] = r2; b[j2 * 2 + 1][1] = r3;
            }
#pragma unroll
            for (int mi = 0; mi < 4; mi++)
#pragma unroll
                for (int j = 0; j < NW; j++)
                    MMA16816(acc[mi][j], a[mi], b[j]);
        }
        const int kn = kk + 2;
        if (kn < NCH) load_chunk(kn, kn % 3);
        CP_COMMIT();
    }

    // ---------------- epilogue ----------------
    const float scale = 1.0f / 48.0f;
    const int r0 = l >> 2, c0 = (l & 3) * 2;
    const int is_m1 = (MODE == 0) && (blockIdx.x == 1);
    const float* bias = is_m1 ? bias1 : bias0;
    float2 bs[NW];
#pragma unroll
    for (int j = 0; j < NW; j++) {
        const int cl = wn * (N_CTA / 4) + j * 8 + c0;   // local co (within block)
        bs[j].x = __ldg(&bias[cl]); bs[j].y = __ldg(&bias[cl + 1]);
    }
#pragma unroll
    for (int mi = 0; mi < 4; mi++) {
#pragma unroll
        for (int h = 0; h < 2; h++) {
            const int p = pix0 + wm * 64 + mi * 16 + r0 + 8 * h;
            const int y = p >> 6, x = p & 63;
#pragma unroll
            for (int j = 0; j < NW; j++) {
                const int cl = wn * (N_CTA / 4) + j * 8 + c0;
                float v0 = acc[mi][j][2 * h]     * scale + bs[j].x;
                float v1 = acc[mi][j][2 * h + 1] * scale + bs[j].y;
                if (MODE == 0) { v0 = fmaxf(v0, 0.f); v1 = fmaxf(v1, 0.f); }
                if (MODE == 0) {
                    if (!is_m1) {
                        ((float*)out0)[((size_t)n * 256 + cl) * 4096 + p] = v0;
                        ((float*)out0)[((size_t)n * 256 + cl + 1) * 4096 + p] = v1;
                    } else {
                        unsigned short h0, l0, h1, l1;
                        split_h(v0, h0, l0); split_h(v1, h1, l1);
                        uint32_t* dst = (uint32_t*)((char*)out1
                            + (((size_t)n * 66 + y + 1) * 66 + (x + 1)) * (CHEXT * 2)
                            + (size_t)cl * 6);
                        dst[0] = (uint32_t)h0 | ((uint32_t)l0 << 16);
                        dst[1] = (uint32_t)h0 | ((uint32_t)h1 << 16);
                        dst[2] = (uint32_t)l1 | ((uint32_t)h1 << 16);
                    }
                } else {
                    const int co = co_base + cl;
                    ((float2*)((float*)out0 + ((size_t)n * 4096 + p) * 576 + co))[0]
                        = make_float2(v0, v1);
                }
            }
        }
    }
}

// ---------------- f2: 3x3 conv 256 -> 2 (fp32 FFMA) ----------------
__global__ __launch_bounds__(256) void conv_small(
    const float* __restrict__ in, const float* __restrict__ wgt,
    const float* __restrict__ bias, float* __restrict__ out)
{
    __shared__ float s_in[8][18][19];
    __shared__ float s_w[8][2][9];
    const int tid = threadIdx.x, n = blockIdx.z;
    const int sbx = blockIdx.x & 3, sby = blockIdx.x >> 2;
    const int row = tid >> 4, cx = tid & 15;
    float acc0 = 0.f, acc1 = 0.f;
    const float* inN = in + (size_t)n * CIN * HS * HS;

    for (int c0 = 0; c0 < CIN; c0 += 8) {
        for (int i = tid; i < 8 * 18 * 18; i += 256) {
            int ci = i / 324, rem = i % 324, r = rem / 18, c = rem % 18;
            int gy = sby * 16 - 1 + r, gx = sbx * 16 - 1 + c;
            float v = 0.f;
            if ((unsigned)gy < 64u && (unsigned)gx < 64u)
                v = inN[(size_t)(c0 + ci) * 4096 + gy * 64 + gx];
            s_in[ci][r][c] = v;
        }
        for (int i = tid; i < 8 * 2 * 9; i += 256) {
            int co = i / 72, rem = i % 72, ci = rem / 9, k = rem % 9;
            s_w[ci][co][k] = wgt[((size_t)co * CIN + c0 + ci) * 9 + k];
        }
        __syncthreads();
        for (int ci = 0; ci < 8; ci++) {
            float iv[3][3];
#pragma unroll
            for (int r2 = 0; r2 < 3; r2++)
#pragma unroll
                for (int c2 = 0; c2 < 3; c2++)
                    iv[r2][c2] = s_in[ci][row + r2][cx + c2];
#pragma unroll
            for (int k = 0; k < 9; k++) {
                acc0 = fmaf(iv[k / 3][k % 3], s_w[ci][0][k], acc0);
                acc1 = fmaf(iv[k / 3][k % 3], s_w[ci][1][k], acc1);
            }
        }
        __syncthreads();
    }
    const float scale = 1.0f / 48.0f;
    const int py = sby * 16 + row, px = sbx * 16 + cx;
    const size_t pix = (size_t)py * 64 + px;
    out[((size_t)n * 2 + 0) * 4096 + pix] = acc0 * scale + bias[0];
    out[((size_t)n * 2 + 1) * 4096 + pix] = acc1 * scale + bias[1];
}

// ---------------- fused upsample + affine + grid_sample ----------------
__global__ __launch_bounds__(512) void fuse_k(
    const float* __restrict__ img, const float* __restrict__ warp,
    float* __restrict__ outBuf)
{
    __shared__ float s_flow[2][3][66];
    __shared__ float s_A[6];
    const int y = blockIdx.x, u = blockIdx.y, n = blockIdx.z;
    const int tid = threadIdx.x;

    if (tid < 6) s_A[tid] = warp[n * 6 + tid];
    for (int i = tid; i < 2 * 3 * 66; i += 512) {
        int c = i / 198, rem = i % 198, r = rem / 66, xx = rem % 66 - 1;
        int yy = y - 1 + r;
        float v = 0.f;
        if ((unsigned)yy < 64u && (unsigned)xx < 64u)
            v = 8.0f * g_flow[(((size_t)n * 2 + c) * 64 + yy) * 64 + xx];
        s_flow[c][r][xx + 1] = v;
    }
    __syncthreads();

    const int x = tid >> 3, v = tid & 7;
    const float* m = &g_mask[((size_t)n * 4096 + (size_t)y * 64 + x) * 576 + u * 8 + v];
    float mk[9];
#pragma unroll
    for (int k = 0; k < 9; k++) mk[k] = m[k * 64];
    float mx = mk[0];
#pragma unroll
    for (int k = 1; k < 9; k++) mx = fmaxf(mx, mk[k]);
    float ssum = 0.f;
#pragma unroll
    for (int k = 0; k < 9; k++) { mk[k] = __expf(mk[k] - mx); ssum += mk[k]; }
    const float inv = 1.0f / ssum;

    float dx = 0.f, dy = 0.f;
#pragma unroll
    for (int k = 0; k < 9; k++) {
        const int ki = k / 3, kj = k % 3;
        const float w = mk[k] * inv;
        dx = fmaf(w, s_flow[0][ki][x + kj], dx);
        dy = fmaf(w, s_flow[1][ki][x + kj], dy);
    }

    const int xf = x * 8 + v, yf = y * 8 + u;
    const float gx = (xf + 0.5f) * (2.0f / 512.0f) - 1.0f + dx;
    const float gy = (yf + 0.5f) * (2.0f / 512.0f) - 1.0f + dy;
    const float fx = s_A[0] * gx + s_A[1] * gy + s_A[2];
    const float fy = s_A[3] * gx + s_A[4] * gy + s_A[5];

    float px = fminf(fmaxf((fx + 1.0f) * 256.0f - 0.5f, 0.f), 511.f);
    float py = fminf(fmaxf((fy + 1.0f) * 256.0f - 0.5f, 0.f), 511.f);
    float x0f = floorf(px), y0f = floorf(py);
    float wx = px - x0f, wy = py - y0f;
    int x0 = (int)x0f, y0 = (int)y0f;
    int x1 = min(x0 + 1, 511), y1 = min(y0 + 1, 511);

    const float* imN = img + (size_t)n * 3 * HF * HF;
#pragma unroll
    for (int c = 0; c < 3; c++) {
        const float* p = imN + (size_t)c * HF * HF;
        float g00 = p[(size_t)y0 * HF + x0], g01 = p[(size_t)y0 * HF + x1];
        float g10 = p[(size_t)y1 * HF + x0], g11 = p[(size_t)y1 * HF + x1];
        float top = g00 + wx * (g01 - g00);
        float bot = g10 + wx * (g11 - g10);
        outBuf[(((size_t)n * 3 + c) * HF + yf) * HF + xf] = top + wy * (bot - top);
    }

    const size_t OFS_FLOW  = (size_t)NB * 3 * HF * HF;
    const size_t OFS_DELTA = OFS_FLOW + (size_t)NB * HF * HF * 2;
    const size_t OFS_FLOW2 = OFS_DELTA + (size_t)NB * HF * HF * 2;
    const size_t fidx = ((size_t)n * HF * HF + (size_t)yf * HF + xf) * 2;
    outBuf[OFS_FLOW  + fidx] = fx;  outBuf[OFS_FLOW  + fidx + 1] = fy;
    outBuf[OFS_DELTA + fidx] = dx;  outBuf[OFS_DELTA + fidx + 1] = dy;
    outBuf[OFS_FLOW2 + fidx] = fx;  outBuf[OFS_FLOW2 + fidx + 1] = fy;
}

// ---------------------------------------------------------------------------
extern "C" void kernel_launch(void* const* d_in, const int* in_sizes, int n_in,
                              void* d_out, int out_size)
{
    const float* img       = (const float*)d_in[0];
    const float* features  = (const float*)d_in[1];
    const float* base_warp = (const float*)d_in[2];
    const float* w_f1 = (const float*)d_in[3];
    const float* b_f1 = (const float*)d_in[4];
    const float* w_f2 = (const float*)d_in[5];
    const float* b_f2 = (const float*)d_in[6];
    const float* w_m1 = (const float*)d_in[7];
    const float* b_m1 = (const float*)d_in[8];
    const float* w_m2 = (const float*)d_in[9];
    const float* b_m2 = (const float*)d_in[10];
    float* out = (float*)d_out;

    void *p_featx, *p_hmx, *p_h, *p_flow, *p_mask, *p_w1x, *p_wm2x;
    cudaGetSymbolAddress(&p_featx, g_featx);
    cudaGetSymbolAddress(&p_hmx,   g_hmx);
    cudaGetSymbolAddress(&p_h,     g_h);
    cudaGetSymbolAddress(&p_flow,  g_flow);
    cudaGetSymbolAddress(&p_mask,  g_mask);
    cudaGetSymbolAddress(&p_w1x,   g_w1x);
    cudaGetSymbolAddress(&p_wm2x,  g_wm2x);

    const int SM256 = 1024 + 3 * (16384 + 256 * 128);   // 148480
    const int SM192 = 1024 + 3 * (16384 + 192 * 128);   // 123904
    cudaFuncSetAttribute(gemm_conv<256, 0>, cudaFuncAttributeMaxDynamicSharedMemorySize, SM256);
    cudaFuncSetAttribute(gemm_conv<192, 2>, cudaFuncAttributeMaxDynamicSharedMemorySize, SM192);

    k_border<<<dim3(260, 16, 2), 256>>>();
    k_featx<<<dim3(128, 8, 16), 256>>>(features);
    k_wext<<<dim3(256, 9), 256>>>(w_f1, (__half*)p_w1x);
    k_wext<<<dim3(256, 9), 256>>>(w_m1, (__half*)p_w1x + (size_t)256 * KEXT);
    k_wext<<<dim3(576, 9), 256>>>(w_m2, (__half*)p_wm2x);

    // fused f1 (blockIdx.x=0) + m1 (blockIdx.x=1)
    gemm_conv<256, 0><<<dim3(2, 512), 256, SM256>>>(
        (const __half*)p_featx, (const __half*)p_w1x, b_f1, b_m1, p_h, p_hmx);
    conv_small<<<dim3(16, 1, NB), 256>>>((const float*)p_h, w_f2, b_f2, (float*)p_flow);
    gemm_conv<192, 2><<<dim3(3, 512), 256, SM192>>>(
        (const __half*)p_hmx, (const __half*)p_wm2x, b_m2, nullptr, p_mask, nullptr);
    fuse_k<<<dim3(64, 8, NB), 512>>>(img, base_warp, out);
}

// round 9
// speedup vs baseline: 4.9217x; 1.0024x over previous
#include <cuda_runtime.h>
#include <cuda_fp16.h>
#include <cstdint>
#include <math.h>

#define NB   16
#define CIN  256
#define HS   64
#define HF   512
#define KEXT 6912            // 9 taps * 256 ci * 3 split slots
#define CHEXT 768            // 256 ci * 3 per tap
#define NCH  108             // KEXT / 64

// ---------------- scratch (__device__ globals; no allocation allowed) ------
__device__ __align__(16) __half g_featx[(size_t)NB * 66 * 66 * CHEXT]; // padded ext features
__device__ __align__(16) __half g_hmx  [(size_t)NB * 66 * 66 * CHEXT]; // padded ext hm
__device__ float g_h   [(size_t)NB * CIN * HS * HS];                   // f1 out fp32 NCHW
__device__ float g_flow[(size_t)NB * 2 * HS * HS];
__device__ float g_mask[(size_t)NB * HS * HS * 576];                   // channel-last
__device__ __align__(16) __half g_w1x [512 * KEXT];                    // rows 0-255 f1, 256-511 m1
__device__ __align__(16) __half g_wm2x[576 * KEXT];

// ---------------- helpers ----------------
__device__ __forceinline__ uint32_t smem_u32(const void* p) {
    uint32_t a;
    asm("{ .reg .u64 t; cvta.to.shared.u64 t, %1; cvt.u32.u64 %0, t; }" : "=r"(a) : "l"(p));
    return a;
}
__device__ __forceinline__ void cpasync16(uint32_t dst, const void* src) {
    asm volatile("cp.async.cg.shared.global [%0], [%1], 16;" :: "r"(dst), "l"(src) : "memory");
}
#define CP_COMMIT() asm volatile("cp.async.commit_group;" ::: "memory")
#define CP_WAIT2()  asm volatile("cp.async.wait_group 2;" ::: "memory")
#define SWZ(o) ((o) ^ (((o) >> 3) & 0x70))

#define LDMX4(r0, r1, r2, r3, addr) \
    asm volatile("ldmatrix.sync.aligned.m8n8.x4.shared.b16 {%0,%1,%2,%3}, [%4];" \
        : "=r"(r0), "=r"(r1), "=r"(r2), "=r"(r3) : "r"(addr))

#define MMA16816(c, a, b) \
    asm volatile("mma.sync.aligned.m16n8k16.row.col.f32.f16.f16.f32 " \
        "{%0,%1,%2,%3},{%4,%5,%6,%7},{%8,%9},{%0,%1,%2,%3};" \
        : "+f"((c)[0]), "+f"((c)[1]), "+f"((c)[2]), "+f"((c)[3]) \
        : "r"((a)[0]), "r"((a)[1]), "r"((a)[2]), "r"((a)[3]), "r"((b)[0]), "r"((b)[1]))

__device__ __forceinline__ void split_h(float v, unsigned short& h, unsigned short& l) {
    __half hh = __float2half_rn(v);
    __half ll = __float2half_rn(v - __half2float(hh));
    h = __half_as_ushort(hh);
    l = __half_as_ushort(ll);
}

// ---------------- prep kernels ----------------
__global__ void k_border() {   // zero 1-px border of both ext buffers
    int p = blockIdx.x, n = blockIdx.y;
    int y, x;
    if (p < 66)       { y = 0;  x = p; }
    else if (p < 132) { y = 65; x = p - 66; }
    else if (p < 196) { y = p - 132 + 1; x = 0; }
    else              { y = p - 196 + 1; x = 65; }
    __half* buf = blockIdx.z ? g_hmx : g_featx;
    uint2* dst = (uint2*)(buf + (((size_t)n * 66 + y) * 66 + x) * CHEXT);
    if (threadIdx.x < 192) dst[threadIdx.x] = make_uint2(0u, 0u);
}

__global__ void k_featx(const float* __restrict__ feat) {
    __shared__ float s[32][33];
    const int n = blockIdx.z, pb = blockIdx.x * 32, cb = blockIdx.y * 32;
    const int tx = threadIdx.x & 31, ty = threadIdx.x >> 5;
#pragma unroll
    for (int i = 0; i < 4; i++)
        s[ty + i * 8][tx] = feat[((size_t)n * 256 + cb + ty + i * 8) * 4096 + pb + tx];
    __syncthreads();
    const int pl = threadIdx.x >> 3, c4 = (threadIdx.x & 7) * 4;
    const int pix = pb + pl, y = pix >> 6, x = pix & 63;
    char* dst = (char*)(g_featx + (((size_t)n * 66 + y + 1) * 66 + (x + 1)) * CHEXT)
                + (size_t)(cb + c4) * 6;
    unsigned short h[4], l[4];
#pragma unroll
    for (int k = 0; k < 4; k++) split_h(s[c4 + k][pl], h[k], l[k]);
    uint2 w0, w1;  // 12 halves: h0 l0 h0 | h1 l1 h1 | h2 l2 h2 | h3 l3 h3
    w0.x = (uint32_t)h[0] | ((uint32_t)l[0] << 16);
    w0.y = (uint32_t)h[0] | ((uint32_t)h[1] << 16);
    uint32_t w2 = (uint32_t)l[1] | ((uint32_t)h[1] << 16);
    w1.x = (uint32_t)h[2] | ((uint32_t)l[2] << 16);
    w1.y = (uint32_t)h[2] | ((uint32_t)h[3] << 16);
    uint32_t w5 = (uint32_t)l[3] | ((uint32_t)h[3] << 16);
    ((uint2*)dst)[0] = w0;
    ((uint32_t*)dst)[2] = w2;
    ((uint2*)(dst + 12))[0] = w1;
    ((uint32_t*)dst)[5] = w5;
}

// rows: f1(0..255)+m1(256..511) -> g_w1x, or m2(0..575) -> g_wm2x
__global__ void k_wext2(const float* __restrict__ wa, const float* __restrict__ wb,
                        __half* __restrict__ wx, int rows_a) {
    const int co = blockIdx.x, tap = blockIdx.y, ci = threadIdx.x;
    const float* src = (co < rows_a) ? wa : wb;
    const int row = (co < rows_a) ? co : co - rows_a;
    float v = src[((size_t)row * 256 + ci) * 9 + tap];
    unsigned short h, l;
    split_h(v, h, l);
    unsigned short* p = (unsigned short*)(wx + (size_t)co * KEXT + tap * CHEXT + ci * 3);
    p[0] = h; p[1] = h; p[2] = l;      // slots: (xh*wh) (xl*wh) (xh*wl)
}

// ---------------- HMMA implicit-GEMM conv ----------------
// CTA tile 128(M) x N_CTA, 8 warps as 2(wm) x 4(wn), warp tile m64 x n(N_CTA/4).
// 4-stage cp.async pipeline.
// MODE 0 (fused f1+m1): blockIdx.x==0 -> fp32 NCHW + relu (g_h);
//                       blockIdx.x==1 -> split-fp16 ext + relu (g_hmx).
// MODE 2: channel-last fp32, no relu (mask).
template<int N_CTA, int MODE>
__global__ __launch_bounds__(256, 1) void gemm_conv(
    const __half* __restrict__ Aext, const __half* __restrict__ Bw,
    const float* __restrict__ bias0, const float* __restrict__ bias1,
    void* __restrict__ out0, void* __restrict__ out1)
{
    constexpr int NW = N_CTA / 32;            // n8 frags per warp (8 or 6)
    constexpr int STAGE_A = 128 * 128;        // bytes
    constexpr int STAGE_B = N_CTA * 128;
    constexpr int STAGE = STAGE_A + STAGE_B;

    extern __shared__ __align__(16) char smraw[];
    uint32_t sb0 = (smem_u32(smraw) + 1023) & ~1023u;

    const int tid = threadIdx.x;
    const int n    = blockIdx.y >> 5;
    const int pix0 = (blockIdx.y & 31) * 128;
    const int co_base = blockIdx.x * N_CTA;

    auto load_chunk = [&](int kk, int st) {
        const int tap = kk / 12, cg = kk % 12;
        const int dy = tap / 3, dx = tap % 3;
        {   // A: 128 pixel rows x 128B
            const int r = tid >> 1, g0 = (tid & 1) * 4;
            const int p = pix0 + r, y = p >> 6, x = p & 63;
            const char* src = (const char*)Aext
                + (((size_t)n * 66 + y + dy) * 66 + (x + dx)) * (CHEXT * 2)
                + (size_t)cg * 128 + g0 * 16;
            const uint32_t base = sb0 + st * STAGE;
#pragma unroll
            for (int i = 0; i < 4; i++)
                cpasync16(base + SWZ((uint32_t)(r * 128 + (g0 + i) * 16)), src + i * 16);
        }
        {   // B: N_CTA co rows x 128B
            const uint32_t base = sb0 + st * STAGE + STAGE_A;
            const char* srcb = (const char*)Bw + ((size_t)tap * CHEXT + cg * 64) * 2;
#pragma unroll
            for (int idx = tid; idx < N_CTA * 8; idx += 256) {
                const int r = idx >> 3, g = idx & 7;
                const char* src = srcb + (size_t)(co_base + r) * (KEXT * 2) + g * 16;
                cpasync16(base + SWZ((uint32_t)(r * 128 + g * 16)), src);
            }
        }
    };

    const int l = tid & 31, wid = tid >> 5;
    const int wm = wid >> 2, wn = wid & 3;

    float acc[4][NW][4];
#pragma unroll
    for (int mi = 0; mi < 4; mi++)
#pragma unroll
        for (int j = 0; j < NW; j++)
#pragma unroll
            for (int q = 0; q < 4; q++) acc[mi][j][q] = 0.f;

    load_chunk(0, 0); CP_COMMIT();
    load_chunk(1, 1); CP_COMMIT();
    load_chunk(2, 2); CP_COMMIT();

    const int arow  = wm * 64 + (l & 7) + ((l >> 3) & 1) * 8;          // + mi*16
    const int aklan = ((l >> 4) & 1) * 16;                             // bytes
    const int brow0 = wn * (N_CTA / 4) + (l & 7) + ((l >> 4) & 1) * 8; // + j2*16
    const int bklan = ((l >> 3) & 1) * 16;

    for (int kk = 0; kk < NCH; kk++) {
        const int st = kk & 3;
        CP_WAIT2();
        __syncthreads();
        const uint32_t a_tile = sb0 + st * STAGE;
        const uint32_t b_tile = a_tile + STAGE_A;
#pragma unroll
        for (int ks = 0; ks < 4; ks++) {
            uint32_t a[4][4];
#pragma unroll
            for (int mi = 0; mi < 4; mi++)
                LDMX4(a[mi][0], a[mi][1], a[mi][2], a[mi][3],
                      a_tile + SWZ((uint32_t)((arow + mi * 16) * 128 + ks * 32 + aklan)));
            uint32_t b[NW][2];
#pragma unroll
            for (int j2 = 0; j2 < NW / 2; j2++) {
                uint32_t r0, r1, r2, r3;
                LDMX4(r0, r1, r2, r3,
                      b_tile + SWZ((uint32_t)((brow0 + j2 * 16) * 128 + ks * 32 + bklan)));
                b[j2 * 2][0] = r0; b[j2 * 2][1] = r1;
                b[j2 * 2 + 1][0] = r2; b[j2 * 2 + 1][1] = r3;
            }
#pragma unroll
            for (int mi = 0; mi < 4; mi++)
#pragma unroll
                for (int j = 0; j < NW; j++)
                    MMA16816(acc[mi][j], a[mi], b[j]);
        }
        const int kn = kk + 3;
        if (kn < NCH) load_chunk(kn, kn & 3);
        CP_COMMIT();   // always commit (possibly empty) to keep group accounting
    }

    // ---------------- epilogue ----------------
    const float scale = 1.0f / 48.0f;
    const int r0 = l >> 2, c0 = (l & 3) * 2;
    const int is_m1 = (MODE == 0) && (blockIdx.x == 1);
    const float* bias = is_m1 ? bias1 : bias0;
    float2 bs[NW];
#pragma unroll
    for (int j = 0; j < NW; j++) {
        const int cl = wn * (N_CTA / 4) + j * 8 + c0;   // local co (within block)
        bs[j].x = __ldg(&bias[cl]); bs[j].y = __ldg(&bias[cl + 1]);
    }
#pragma unroll
    for (int mi = 0; mi < 4; mi++) {
#pragma unroll
        for (int h = 0; h < 2; h++) {
            const int p = pix0 + wm * 64 + mi * 16 + r0 + 8 * h;
            const int y = p >> 6, x = p & 63;
#pragma unroll
            for (int j = 0; j < NW; j++) {
                const int cl = wn * (N_CTA / 4) + j * 8 + c0;
                float v0 = acc[mi][j][2 * h]     * scale + bs[j].x;
                float v1 = acc[mi][j][2 * h + 1] * scale + bs[j].y;
                if (MODE == 0) { v0 = fmaxf(v0, 0.f); v1 = fmaxf(v1, 0.f); }
                if (MODE == 0) {
                    if (!is_m1) {
                        ((float*)out0)[((size_t)n * 256 + cl) * 4096 + p] = v0;
                        ((float*)out0)[((size_t)n * 256 + cl + 1) * 4096 + p] = v1;
                    } else {
                        unsigned short h0, l0, h1, l1;
                        split_h(v0, h0, l0); split_h(v1, h1, l1);
                        uint32_t* dst = (uint32_t*)((char*)out1
                            + (((size_t)n * 66 + y + 1) * 66 + (x + 1)) * (CHEXT * 2)
                            + (size_t)cl * 6);
                        dst[0] = (uint32_t)h0 | ((uint32_t)l0 << 16);
                        dst[1] = (uint32_t)h0 | ((uint32_t)h1 << 16);
                        dst[2] = (uint32_t)l1 | ((uint32_t)h1 << 16);
                    }
                } else {
                    const int co = co_base + cl;
                    ((float2*)((float*)out0 + ((size_t)n * 4096 + p) * 576 + co))[0]
                        = make_float2(v0, v1);
                }
            }
        }
    }
}

// ---------------- f2: 3x3 conv 256 -> 2 (fp32 FFMA) ----------------
__global__ __launch_bounds__(256) void conv_small(
    const float* __restrict__ in, const float* __restrict__ wgt,
    const float* __restrict__ bias, float* __restrict__ out)
{
    __shared__ float s_in[8][18][19];
    __shared__ float s_w[8][2][9];
    const int tid = threadIdx.x, n = blockIdx.z;
    const int sbx = blockIdx.x & 3, sby = blockIdx.x >> 2;
    const int row = tid >> 4, cx = tid & 15;
    float acc0 = 0.f, acc1 = 0.f;
    const float* inN = in + (size_t)n * CIN * HS * HS;

    for (int c0 = 0; c0 < CIN; c0 += 8) {
        for (int i = tid; i < 8 * 18 * 18; i += 256) {
            int ci = i / 324, rem = i % 324, r = rem / 18, c = rem % 18;
            int gy = sby * 16 - 1 + r, gx = sbx * 16 - 1 + c;
            float v = 0.f;
            if ((unsigned)gy < 64u && (unsigned)gx < 64u)
                v = inN[(size_t)(c0 + ci) * 4096 + gy * 64 + gx];
            s_in[ci][r][c] = v;
        }
        for (int i = tid; i < 8 * 2 * 9; i += 256) {
            int co = i / 72, rem = i % 72, ci = rem / 9, k = rem % 9;
            s_w[ci][co][k] = wgt[((size_t)co * CIN + c0 + ci) * 9 + k];
        }
        __syncthreads();
        for (int ci = 0; ci < 8; ci++) {
            float iv[3][3];
#pragma unroll
            for (int r2 = 0; r2 < 3; r2++)
#pragma unroll
                for (int c2 = 0; c2 < 3; c2++)
                    iv[r2][c2] = s_in[ci][row + r2][cx + c2];
#pragma unroll
            for (int k = 0; k < 9; k++) {
                acc0 = fmaf(iv[k / 3][k % 3], s_w[ci][0][k], acc0);
                acc1 = fmaf(iv[k / 3][k % 3], s_w[ci][1][k], acc1);
            }
        }
        __syncthreads();
    }
    const float scale = 1.0f / 48.0f;
    const int py = sby * 16 + row, px = sbx * 16 + cx;
    const size_t pix = (size_t)py * 64 + px;
    out[((size_t)n * 2 + 0) * 4096 + pix] = acc0 * scale + bias[0];
    out[((size_t)n * 2 + 1) * 4096 + pix] = acc1 * scale + bias[1];
}

// ---------------- fused upsample + affine + grid_sample ----------------
__global__ __launch_bounds__(512) void fuse_k(
    const float* __restrict__ img, const float* __restrict__ warp,
    float* __restrict__ outBuf)
{
    __shared__ float s_flow[2][3][66];
    __shared__ float s_A[6];
    const int y = blockIdx.x, u = blockIdx.y, n = blockIdx.z;
    const int tid = threadIdx.x;

    if (tid < 6) s_A[tid] = warp[n * 6 + tid];
    for (int i = tid; i < 2 * 3 * 66; i += 512) {
        int c = i / 198, rem = i % 198, r = rem / 66, xx = rem % 66 - 1;
        int yy = y - 1 + r;
        float v = 0.f;
        if ((unsigned)yy < 64u && (unsigned)xx < 64u)
            v = 8.0f * g_flow[(((size_t)n * 2 + c) * 64 + yy) * 64 + xx];
        s_flow[c][r][xx + 1] = v;
    }
    __syncthreads();

    const int x = tid >> 3, v = tid & 7;
    const float* m = &g_mask[((size_t)n * 4096 + (size_t)y * 64 + x) * 576 + u * 8 + v];
    float mk[9];
#pragma unroll
    for (int k = 0; k < 9; k++) mk[k] = m[k * 64];
    float mx = mk[0];
#pragma unroll
    for (int k = 1; k < 9; k++) mx = fmaxf(mx, mk[k]);
    float ssum = 0.f;
#pragma unroll
    for (int k = 0; k < 9; k++) { mk[k] = __expf(mk[k] - mx); ssum += mk[k]; }
    const float inv = 1.0f / ssum;

    float dx = 0.f, dy = 0.f;
#pragma unroll
    for (int k = 0; k < 9; k++) {
        const int ki = k / 3, kj = k % 3;
        const float w = mk[k] * inv;
        dx = fmaf(w, s_flow[0][ki][x + kj], dx);
        dy = fmaf(w, s_flow[1][ki][x + kj], dy);
    }

    const int xf = x * 8 + v, yf = y * 8 + u;
    const float gx = (xf + 0.5f) * (2.0f / 512.0f) - 1.0f + dx;
    const float gy = (yf + 0.5f) * (2.0f / 512.0f) - 1.0f + dy;
    const float fx = s_A[0] * gx + s_A[1] * gy + s_A[2];
    const float fy = s_A[3] * gx + s_A[4] * gy + s_A[5];

    float px = fminf(fmaxf((fx + 1.0f) * 256.0f - 0.5f, 0.f), 511.f);
    float py = fminf(fmaxf((fy + 1.0f) * 256.0f - 0.5f, 0.f), 511.f);
    float x0f = floorf(px), y0f = floorf(py);
    float wx = px - x0f, wy = py - y0f;
    int x0 = (int)x0f, y0 = (int)y0f;
    int x1 = min(x0 + 1, 511), y1 = min(y0 + 1, 511);

    const float* imN = img + (size_t)n * 3 * HF * HF;
#pragma unroll
    for (int c = 0; c < 3; c++) {
        const float* p = imN + (size_t)c * HF * HF;
        float g00 = p[(size_t)y0 * HF + x0], g01 = p[(size_t)y0 * HF + x1];
        float g10 = p[(size_t)y1 * HF + x0], g11 = p[(size_t)y1 * HF + x1];
        float top = g00 + wx * (g01 - g00);
        float bot = g10 + wx * (g11 - g10);
        outBuf[(((size_t)n * 3 + c) * HF + yf) * HF + xf] = top + wy * (bot - top);
    }

    const size_t OFS_FLOW  = (size_t)NB * 3 * HF * HF;
    const size_t OFS_DELTA = OFS_FLOW + (size_t)NB * HF * HF * 2;
    const size_t OFS_FLOW2 = OFS_DELTA + (size_t)NB * HF * HF * 2;
    const size_t fidx = ((size_t)n * HF * HF + (size_t)yf * HF + xf) * 2;
    outBuf[OFS_FLOW  + fidx] = fx;  outBuf[OFS_FLOW  + fidx + 1] = fy;
    outBuf[OFS_DELTA + fidx] = dx;  outBuf[OFS_DELTA + fidx + 1] = dy;
    outBuf[OFS_FLOW2 + fidx] = fx;  outBuf[OFS_FLOW2 + fidx + 1] = fy;
}

// ---------------------------------------------------------------------------
extern "C" void kernel_launch(void* const* d_in, const int* in_sizes, int n_in,
                              void* d_out, int out_size)
{
    const float* img       = (const float*)d_in[0];
    const float* features  = (const float*)d_in[1];
    const float* base_warp = (const float*)d_in[2];
    const float* w_f1 = (const float*)d_in[3];
    const float* b_f1 = (const float*)d_in[4];
    const float* w_f2 = (const float*)d_in[5];
    const float* b_f2 = (const float*)d_in[6];
    const float* w_m1 = (const float*)d_in[7];
    const float* b_m1 = (const float*)d_in[8];
    const float* w_m2 = (const float*)d_in[9];
    const float* b_m2 = (const float*)d_in[10];
    float* out = (float*)d_out;

    void *p_featx, *p_hmx, *p_h, *p_flow, *p_mask, *p_w1x, *p_wm2x;
    cudaGetSymbolAddress(&p_featx, g_featx);
    cudaGetSymbolAddress(&p_hmx,   g_hmx);
    cudaGetSymbolAddress(&p_h,     g_h);
    cudaGetSymbolAddress(&p_flow,  g_flow);
    cudaGetSymbolAddress(&p_mask,  g_mask);
    cudaGetSymbolAddress(&p_w1x,   g_w1x);
    cudaGetSymbolAddress(&p_wm2x,  g_wm2x);

    const int SM256 = 1024 + 4 * (16384 + 256 * 128);   // 197632
    const int SM192 = 1024 + 4 * (16384 + 192 * 128);   // 164864
    cudaFuncSetAttribute(gemm_conv<256, 0>, cudaFuncAttributeMaxDynamicSharedMemorySize, SM256);
    cudaFuncSetAttribute(gemm_conv<192, 2>, cudaFuncAttributeMaxDynamicSharedMemorySize, SM192);

    k_border<<<dim3(260, 16, 2), 256>>>();
    k_featx<<<dim3(128, 8, 16), 256>>>(features);
    k_wext2<<<dim3(512, 9), 256>>>(w_f1, w_m1, (__half*)p_w1x, 256);
    k_wext2<<<dim3(576, 9), 256>>>(w_m2, w_m2, (__half*)p_wm2x, 576);

    // fused f1 (blockIdx.x=0) + m1 (blockIdx.x=1)
    gemm_conv<256, 0><<<dim3(2, 512), 256, SM256>>>(
        (const __half*)p_featx, (const __half*)p_w1x, b_f1, b_m1, p_h, p_hmx);
    gemm_conv<192, 2><<<dim3(3, 512), 256, SM192>>>(
        (const __half*)p_hmx, (const __half*)p_wm2x, b_m2, nullptr, p_mask, nullptr);
    conv_small<<<dim3(16, 1, NB), 256>>>((const float*)p_h, w_f2, b_f2, (float*)p_flow);
    fuse_k<<<dim3(64, 8, NB), 512>>>(img, base_warp, out);
}

// round 13
// speedup vs baseline: 4.9325x; 1.0022x over previous
#include <cuda_runtime.h>
#include <cuda_fp16.h>
#include <cstdint>
#include <math.h>

#define NB   16
#define CIN  256
#define HS   64
#define HF   512
#define KEXT 6912            // 9 taps * 256 ci * 3 split slots
#define CHEXT 768            // per-tap ext channels
#define NCH  108             // KEXT / 64

// ---------------- scratch (__device__ globals; no allocation allowed) ------
__device__ __align__(16) __half g_featx[(size_t)NB * 66 * 66 * CHEXT]; // padded ext features
__device__ __align__(16) __half g_hmx  [(size_t)NB * 66 * 66 * CHEXT]; // padded ext hm
__device__ float g_h   [(size_t)NB * CIN * HS * HS];                   // f1 out fp32 NCHW
__device__ float g_flow[(size_t)NB * 2 * HS * HS];
__device__ float g_mask[(size_t)NB * HS * HS * 576];                   // channel-last
__device__ __align__(16) __half g_w1x [512 * KEXT];                    // rows 0-255 f1, 256-511 m1
__device__ __align__(16) __half g_wm2x[576 * KEXT];

// ---------------- helpers ----------------
__device__ __forceinline__ uint32_t smem_u32(const void* p) {
    uint32_t a;
    asm("{ .reg .u64 t; cvta.to.shared.u64 t, %1; cvt.u32.u64 %0, t; }" : "=r"(a) : "l"(p));
    return a;
}
__device__ __forceinline__ void cpasync16(uint32_t dst, const void* src) {
    asm volatile("cp.async.cg.shared.global [%0], [%1], 16;" :: "r"(dst), "l"(src) : "memory");
}
#define CP_COMMIT() asm volatile("cp.async.commit_group;" ::: "memory")
#define CP_WAIT2()  asm volatile("cp.async.wait_group 2;" ::: "memory")
#define SWZ(o) ((o) ^ (((o) >> 3) & 0x70))

#define LDMX4(r0, r1, r2, r3, addr) \
    asm volatile("ldmatrix.sync.aligned.m8n8.x4.shared.b16 {%0,%1,%2,%3}, [%4];" \
        : "=r"(r0), "=r"(r1), "=r"(r2), "=r"(r3) : "r"(addr))

#define MMA16816(c, a, b) \
    asm volatile("mma.sync.aligned.m16n8k16.row.col.f32.f16.f16.f32 " \
        "{%0,%1,%2,%3},{%4,%5,%6,%7},{%8,%9},{%0,%1,%2,%3};" \
        : "+f"((c)[0]), "+f"((c)[1]), "+f"((c)[2]), "+f"((c)[3]) \
        : "r"((a)[0]), "r"((a)[1]), "r"((a)[2]), "r"((a)[3]), "r"((b)[0]), "r"((b)[1]))

__device__ __forceinline__ void split_h(float v, unsigned short& h, unsigned short& l) {
    __half hh = __float2half_rn(v);
    __half ll = __float2half_rn(v - __half2float(hh));
    h = __half_as_ushort(hh);
    l = __half_as_ushort(ll);
}

// ---------------- prep kernels (merged: 2 launches total) ----------------
// prep_w: all weight ext. co<256 -> f1 row, co<512 -> m1 row (both g_w1x),
// co>=512 -> m2 row co-512 (g_wm2x). 3-slot: [wh, wh, wl].
__global__ void prep_w(const float* __restrict__ wf1, const float* __restrict__ wm1,
                       const float* __restrict__ wm2) {
    const int co = blockIdx.x, tap = blockIdx.y, ci = threadIdx.x;
    const float* src;
    int row;
    __half* wx;
    int orow;
    if (co < 256)      { src = wf1; row = co;       wx = g_w1x;  orow = co; }
    else if (co < 512) { src = wm1; row = co - 256; wx = g_w1x;  orow = co; }
    else               { src = wm2; row = co - 512; wx = g_wm2x; orow = co - 512; }
    float v = src[((size_t)row * 256 + ci) * 9 + tap];
    unsigned short h, l;
    split_h(v, h, l);
    unsigned short* p = (unsigned short*)(wx + (size_t)orow * KEXT + tap * CHEXT + ci * 3);
    p[0] = h; p[1] = h; p[2] = l;      // slots: (xh*wh) (xl*wh) (xh*wl)
}

// prep_feat: blockIdx.y<8 -> feature ext (split+pack); y>=8 -> border zeroing
// of both ext buffers (520 border units per n mapped onto 5*128 blocks).
__global__ void prep_feat(const float* __restrict__ feat) {
    const int n = blockIdx.z;
    if (blockIdx.y < 8) {
        __shared__ float s[32][33];
        const int pb = blockIdx.x * 32, cb = blockIdx.y * 32;
        const int tx = threadIdx.x & 31, ty = threadIdx.x >> 5;
#pragma unroll
        for (int i = 0; i < 4; i++)
            s[ty + i * 8][tx] = feat[((size_t)n * 256 + cb + ty + i * 8) * 4096 + pb + tx];
        __syncthreads();
        const int pl = threadIdx.x >> 3, c4 = (threadIdx.x & 7) * 4;
        const int pix = pb + pl, y = pix >> 6, x = pix & 63;
        char* dst = (char*)(g_featx + (((size_t)n * 66 + y + 1) * 66 + (x + 1)) * CHEXT)
                    + (size_t)(cb + c4) * 6;
        unsigned short h[4], l[4];
#pragma unroll
        for (int k = 0; k < 4; k++) split_h(s[c4 + k][pl], h[k], l[k]);
        uint2 w0, w1;  // 12 halves: h0 l0 h0 | h1 l1 h1 | h2 l2 h2 | h3 l3 h3
        w0.x = (uint32_t)h[0] | ((uint32_t)l[0] << 16);
        w0.y = (uint32_t)h[0] | ((uint32_t)h[1] << 16);
        uint32_t w2 = (uint32_t)l[1] | ((uint32_t)h[1] << 16);
        w1.x = (uint32_t)h[2] | ((uint32_t)l[2] << 16);
        w1.y = (uint32_t)h[2] | ((uint32_t)h[3] << 16);
        uint32_t w5 = (uint32_t)l[3] | ((uint32_t)h[3] << 16);
        ((uint2*)dst)[0] = w0;
        ((uint32_t*)dst)[2] = w2;
        ((uint2*)(dst + 12))[0] = w1;
        ((uint32_t*)dst)[5] = w5;
    } else {
        const int idx = (blockIdx.y - 8) * 128 + blockIdx.x;   // 0..639
        if (idx >= 520) return;
        const int which = idx >= 260;           // 0 -> g_featx, 1 -> g_hmx
        const int p = which ? idx - 260 : idx;  // 0..259
        int y, x;
        if (p < 66)       { y = 0;  x = p; }
        else if (p < 132) { y = 65; x = p - 66; }
        else if (p < 196) { y = p - 132 + 1; x = 0; }
        else              { y = p - 196 + 1; x = 65; }
        __half* buf = which ? g_hmx : g_featx;
        uint2* dst = (uint2*)(buf + (((size_t)n * 66 + y) * 66 + x) * CHEXT);
        if (threadIdx.x < 192) dst[threadIdx.x] = make_uint2(0u, 0u);
    }
}

// ---------------- HMMA implicit-GEMM conv ----------------
// CTA tile 128(M) x N_CTA, 8 warps as 2(wm) x 4(wn), warp tile m64 x n(N_CTA/4).
// 4-stage cp.async pipeline.
// MODE 0 (fused f1+m1): blockIdx.x==0 -> fp32 NCHW + relu (g_h);
//                       blockIdx.x==1 -> split-fp16 ext + relu (g_hmx).
// MODE 2: channel-last fp32, no relu (mask).
template<int N_CTA, int MODE>
__global__ __launch_bounds__(256, 1) void gemm_conv(
    const __half* __restrict__ Aext, const __half* __restrict__ Bw,
    const float* __restrict__ bias0, const float* __restrict__ bias1,
    void* __restrict__ out0, void* __restrict__ out1)
{
    constexpr int NW = N_CTA / 32;            // n8 frags per warp (8 or 6)
    constexpr int STAGE_A = 128 * 128;        // bytes
    constexpr int STAGE_B = N_CTA * 128;
    constexpr int STAGE = STAGE_A + STAGE_B;

    extern __shared__ __align__(16) char smraw[];
    uint32_t sb0 = (smem_u32(smraw) + 1023) & ~1023u;

    const int tid = threadIdx.x;
    const int n    = blockIdx.y >> 5;
    const int pix0 = (blockIdx.y & 31) * 128;
    const int co_base = blockIdx.x * N_CTA;

    auto load_chunk = [&](int kk, int st) {
        const int tap = kk / 12, cg = kk % 12;
        const int dy = tap / 3, dx = tap % 3;
        {   // A: 128 pixel rows x 128B
            const int r = tid >> 1, g0 = (tid & 1) * 4;
            const int p = pix0 + r, y = p >> 6, x = p & 63;
            const char* src = (const char*)Aext
                + (((size_t)n * 66 + y + dy) * 66 + (x + dx)) * (CHEXT * 2)
                + (size_t)cg * 128 + g0 * 16;
            const uint32_t base = sb0 + st * STAGE;
#pragma unroll
            for (int i = 0; i < 4; i++)
                cpasync16(base + SWZ((uint32_t)(r * 128 + (g0 + i) * 16)), src + i * 16);
        }
        {   // B: N_CTA co rows x 128B
            const uint32_t base = sb0 + st * STAGE + STAGE_A;
            const char* srcb = (const char*)Bw + ((size_t)tap * CHEXT + cg * 64) * 2;
#pragma unroll
            for (int idx = tid; idx < N_CTA * 8; idx += 256) {
                const int r = idx >> 3, g = idx & 7;
                const char* src = srcb + (size_t)(co_base + r) * (KEXT * 2) + g * 16;
                cpasync16(base + SWZ((uint32_t)(r * 128 + g * 16)), src);
            }
        }
    };

    const int l = tid & 31, wid = tid >> 5;
    const int wm = wid >> 2, wn = wid & 3;

    float acc[4][NW][4];
#pragma unroll
    for (int mi = 0; mi < 4; mi++)
#pragma unroll
        for (int j = 0; j < NW; j++)
#pragma unroll
            for (int q = 0; q < 4; q++) acc[mi][j][q] = 0.f;

    load_chunk(0, 0); CP_COMMIT();
    load_chunk(1, 1); CP_COMMIT();
    load_chunk(2, 2); CP_COMMIT();

    const int arow  = wm * 64 + (l & 7) + ((l >> 3) & 1) * 8;          // + mi*16
    const int aklan = ((l >> 4) & 1) * 16;                             // bytes
    const int brow0 = wn * (N_CTA / 4) + (l & 7) + ((l >> 4) & 1) * 8; // + j2*16
    const int bklan = ((l >> 3) & 1) * 16;

    for (int kk = 0; kk < NCH; kk++) {
        const int st = kk & 3;
        CP_WAIT2();
        __syncthreads();
        const uint32_t a_tile = sb0 + st * STAGE;
        const uint32_t b_tile = a_tile + STAGE_A;
#pragma unroll
        for (int ks = 0; ks < 4; ks++) {
            uint32_t a[4][4];
#pragma unroll
            for (int mi = 0; mi < 4; mi++)
                LDMX4(a[mi][0], a[mi][1], a[mi][2], a[mi][3],
                      a_tile + SWZ((uint32_t)((arow + mi * 16) * 128 + ks * 32 + aklan)));
            uint32_t b[NW][2];
#pragma unroll
            for (int j2 = 0; j2 < NW / 2; j2++) {
                uint32_t r0, r1, r2, r3;
                LDMX4(r0, r1, r2, r3,
                      b_tile + SWZ((uint32_t)((brow0 + j2 * 16) * 128 + ks * 32 + bklan)));
                b[j2 * 2][0] = r0; b[j2 * 2][1] = r1;
                b[j2 * 2 + 1][0] = r2; b[j2 * 2 + 1][1] = r3;
            }
#pragma unroll
            for (int mi = 0; mi < 4; mi++)
#pragma unroll
                for (int j = 0; j < NW; j++)
                    MMA16816(acc[mi][j], a[mi], b[j]);
        }
        const int kn = kk + 3;
        if (kn < NCH) load_chunk(kn, kn & 3);
        CP_COMMIT();   // always commit (possibly empty) to keep group accounting
    }

    // ---------------- epilogue ----------------
    const float scale = 1.0f / 48.0f;
    const int r0 = l >> 2, c0 = (l & 3) * 2;
    const int is_m1 = (MODE == 0) && (blockIdx.x == 1);
    const float* bias = is_m1 ? bias1 : bias0;
    float2 bs[NW];
#pragma unroll
    for (int j = 0; j < NW; j++) {
        const int cl = wn * (N_CTA / 4) + j * 8 + c0;   // local co (within block)
        bs[j].x = __ldg(&bias[cl]); bs[j].y = __ldg(&bias[cl + 1]);
    }
#pragma unroll
    for (int mi = 0; mi < 4; mi++) {
#pragma unroll
        for (int h = 0; h < 2; h++) {
            const int p = pix0 + wm * 64 + mi * 16 + r0 + 8 * h;
            const int y = p >> 6, x = p & 63;
#pragma unroll
            for (int j = 0; j < NW; j++) {
                const int cl = wn * (N_CTA / 4) + j * 8 + c0;
                float v0 = acc[mi][j][2 * h]     * scale + bs[j].x;
                float v1 = acc[mi][j][2 * h + 1] * scale + bs[j].y;
                if (MODE == 0) { v0 = fmaxf(v0, 0.f); v1 = fmaxf(v1, 0.f); }
                if (MODE == 0) {
                    if (!is_m1) {
                        ((float*)out0)[((size_t)n * 256 + cl) * 4096 + p] = v0;
                        ((float*)out0)[((size_t)n * 256 + cl + 1) * 4096 + p] = v1;
                    } else {
                        unsigned short h0, l0, h1, l1;
                        split_h(v0, h0, l0); split_h(v1, h1, l1);
                        uint32_t* dst = (uint32_t*)((char*)out1
                            + (((size_t)n * 66 + y + 1) * 66 + (x + 1)) * (CHEXT * 2)
                            + (size_t)cl * 6);
                        dst[0] = (uint32_t)h0 | ((uint32_t)l0 << 16);
                        dst[1] = (uint32_t)h0 | ((uint32_t)h1 << 16);
                        dst[2] = (uint32_t)l1 | ((uint32_t)h1 << 16);
                    }
                } else {
                    const int co = co_base + cl;
                    ((float2*)((float*)out0 + ((size_t)n * 4096 + p) * 576 + co))[0]
                        = make_float2(v0, v1);
                }
            }
        }
    }
}

// ---------------- f2: 3x3 conv 256 -> 2 (fp32 FFMA) ----------------
__global__ __launch_bounds__(256) void conv_small(
    const float* __restrict__ in, const float* __restrict__ wgt,
    const float* __restrict__ bias, float* __restrict__ out)
{
    __shared__ float s_in[8][18][19];
    __shared__ float s_w[8][2][9];
    const int tid = threadIdx.x, n = blockIdx.z;
    const int sbx = blockIdx.x & 3, sby = blockIdx.x >> 2;
    const int row = tid >> 4, cx = tid & 15;
    float acc0 = 0.f, acc1 = 0.f;
    const float* inN = in + (size_t)n * CIN * HS * HS;

    for (int c0 = 0; c0 < CIN; c0 += 8) {
        for (int i = tid; i < 8 * 18 * 18; i += 256) {
            int ci = i / 324, rem = i % 324, r = rem / 18, c = rem % 18;
            int gy = sby * 16 - 1 + r, gx = sbx * 16 - 1 + c;
            float v = 0.f;
            if ((unsigned)gy < 64u && (unsigned)gx < 64u)
                v = inN[(size_t)(c0 + ci) * 4096 + gy * 64 + gx];
            s_in[ci][r][c] = v;
        }
        for (int i = tid; i < 8 * 2 * 9; i += 256) {
            int co = i / 72, rem = i % 72, ci = rem / 9, k = rem % 9;
            s_w[ci][co][k] = wgt[((size_t)co * CIN + c0 + ci) * 9 + k];
        }
        __syncthreads();
        for (int ci = 0; ci < 8; ci++) {
            float iv[3][3];
#pragma unroll
            for (int r2 = 0; r2 < 3; r2++)
#pragma unroll
                for (int c2 = 0; c2 < 3; c2++)
                    iv[r2][c2] = s_in[ci][row + r2][cx + c2];
#pragma unroll
            for (int k = 0; k < 9; k++) {
                acc0 = fmaf(iv[k / 3][k % 3], s_w[ci][0][k], acc0);
                acc1 = fmaf(iv[k / 3][k % 3], s_w[ci][1][k], acc1);
            }
        }
        __syncthreads();
    }
    const float scale = 1.0f / 48.0f;
    const int py = sby * 16 + row, px = sbx * 16 + cx;
    const size_t pix = (size_t)py * 64 + px;
    out[((size_t)n * 2 + 0) * 4096 + pix] = acc0 * scale + bias[0];
    out[((size_t)n * 2 + 1) * 4096 + pix] = acc1 * scale + bias[1];
}

// ---------------- fused upsample + affine + grid_sample ----------------
__global__ __launch_bounds__(512) void fuse_k(
    const float* __restrict__ img, const float* __restrict__ warp,
    float* __restrict__ outBuf)
{
    __shared__ float s_flow[2][3][66];
    __shared__ float s_A[6];
    const int y = blockIdx.x, u = blockIdx.y, n = blockIdx.z;
    const int tid = threadIdx.x;

    if (tid < 6) s_A[tid] = warp[n * 6 + tid];
    for (int i = tid; i < 2 * 3 * 66; i += 512) {
        int c = i / 198, rem = i % 198, r = rem / 66, xx = rem % 66 - 1;
        int yy = y - 1 + r;
        float v = 0.f;
        if ((unsigned)yy < 64u && (unsigned)xx < 64u)
            v = 8.0f * g_flow[(((size_t)n * 2 + c) * 64 + yy) * 64 + xx];
        s_flow[c][r][xx + 1] = v;
    }
    __syncthreads();

    const int x = tid >> 3, v = tid & 7;
    const float* m = &g_mask[((size_t)n * 4096 + (size_t)y * 64 + x) * 576 + u * 8 + v];
    float mk[9];
#pragma unroll
    for (int k = 0; k < 9; k++) mk[k] = m[k * 64];
    float mx = mk[0];
#pragma unroll
    for (int k = 1; k < 9; k++) mx = fmaxf(mx, mk[k]);
    float ssum = 0.f;
#pragma unroll
    for (int k = 0; k < 9; k++) { mk[k] = __expf(mk[k] - mx); ssum += mk[k]; }
    const float inv = 1.0f / ssum;

    float dx = 0.f, dy = 0.f;
#pragma unroll
    for (int k = 0; k < 9; k++) {
        const int ki = k / 3, kj = k % 3;
        const float w = mk[k] * inv;
        dx = fmaf(w, s_flow[0][ki][x + kj], dx);
        dy = fmaf(w, s_flow[1][ki][x + kj], dy);
    }

    const int xf = x * 8 + v, yf = y * 8 + u;
    const float gx = (xf + 0.5f) * (2.0f / 512.0f) - 1.0f + dx;
    const float gy = (yf + 0.5f) * (2.0f / 512.0f) - 1.0f + dy;
    const float fx = s_A[0] * gx + s_A[1] * gy + s_A[2];
    const float fy = s_A[3] * gx + s_A[4] * gy + s_A[5];

    float px = fminf(fmaxf((fx + 1.0f) * 256.0f - 0.5f, 0.f), 511.f);
    float py = fminf(fmaxf((fy + 1.0f) * 256.0f - 0.5f, 0.f), 511.f);
    float x0f = floorf(px), y0f = floorf(py);
    float wx = px - x0f, wy = py - y0f;
    int x0 = (int)x0f, y0 = (int)y0f;
    int x1 = min(x0 + 1, 511), y1 = min(y0 + 1, 511);

    const float* imN = img + (size_t)n * 3 * HF * HF;
#pragma unroll
    for (int c = 0; c < 3; c++) {
        const float* p = imN + (size_t)c * HF * HF;
        float g00 = p[(size_t)y0 * HF + x0], g01 = p[(size_t)y0 * HF + x1];
        float g10 = p[(size_t)y1 * HF + x0], g11 = p[(size_t)y1 * HF + x1];
        float top = g00 + wx * (g01 - g00);
        float bot = g10 + wx * (g11 - g10);
        outBuf[(((size_t)n * 3 + c) * HF + yf) * HF + xf] = top + wy * (bot - top);
    }

    const size_t OFS_FLOW  = (size_t)NB * 3 * HF * HF;
    const size_t OFS_DELTA = OFS_FLOW + (size_t)NB * HF * HF * 2;
    const size_t OFS_FLOW2 = OFS_DELTA + (size_t)NB * HF * HF * 2;
    const size_t fidx = ((size_t)n * HF * HF + (size_t)yf * HF + xf) * 2;
    outBuf[OFS_FLOW  + fidx] = fx;  outBuf[OFS_FLOW  + fidx + 1] = fy;
    outBuf[OFS_DELTA + fidx] = dx;  outBuf[OFS_DELTA + fidx + 1] = dy;
    outBuf[OFS_FLOW2 + fidx] = fx;  outBuf[OFS_FLOW2 + fidx + 1] = fy;
}

// ---------------------------------------------------------------------------
extern "C" void kernel_launch(void* const* d_in, const int* in_sizes, int n_in,
                              void* d_out, int out_size)
{
    const float* img       = (const float*)d_in[0];
    const float* features  = (const float*)d_in[1];
    const float* base_warp = (const float*)d_in[2];
    const float* w_f1 = (const float*)d_in[3];
    const float* b_f1 = (const float*)d_in[4];
    const float* w_f2 = (const float*)d_in[5];
    const float* b_f2 = (const float*)d_in[6];
    const float* w_m1 = (const float*)d_in[7];
    const float* b_m1 = (const float*)d_in[8];
    const float* w_m2 = (const float*)d_in[9];
    const float* b_m2 = (const float*)d_in[10];
    float* out = (float*)d_out;

    void *p_featx, *p_hmx, *p_h, *p_flow, *p_mask, *p_w1x, *p_wm2x;
    cudaGetSymbolAddress(&p_featx, g_featx);
    cudaGetSymbolAddress(&p_hmx,   g_hmx);
    cudaGetSymbolAddress(&p_h,     g_h);
    cudaGetSymbolAddress(&p_flow,  g_flow);
    cudaGetSymbolAddress(&p_mask,  g_mask);
    cudaGetSymbolAddress(&p_w1x,   g_w1x);
    cudaGetSymbolAddress(&p_wm2x,  g_wm2x);

    const int SM256 = 1024 + 4 * (16384 + 256 * 128);   // 197632
    const int SM192 = 1024 + 4 * (16384 + 192 * 128);   // 164864
    cudaFuncSetAttribute(gemm_conv<256, 0>, cudaFuncAttributeMaxDynamicSharedMemorySize, SM256);
    cudaFuncSetAttribute(gemm_conv<192, 2>, cudaFuncAttributeMaxDynamicSharedMemorySize, SM192);

    // launch 0: all weight ext; launch 1: feature ext + border zeroing
    prep_w<<<dim3(1088, 9), 256>>>(w_f1, w_m1, w_m2);
    prep_feat<<<dim3(128, 13, 16), 256>>>(features);

    // launch 2 (ncu capture slot): fused f1 (blockIdx.x=0) + m1 (blockIdx.x=1)
    gemm_conv<256, 0><<<dim3(2, 512), 256, SM256>>>(
        (const __half*)p_featx, (const __half*)p_w1x, b_f1, b_m1, p_h, p_hmx);
    // launch 3: m2 mask GEMM (3-slot)
    gemm_conv<192, 2><<<dim3(3, 512), 256, SM192>>>(
        (const __half*)p_hmx, (const __half*)p_wm2x, b_m2, nullptr, p_mask, nullptr);
    conv_small<<<dim3(16, 1, NB), 256>>>((const float*)p_h, w_f2, b_f2, (float*)p_flow);
    fuse_k<<<dim3(64, 8, NB), 512>>>(img, base_warp, out);
}